// round 6
// baseline (speedup 1.0000x reference)
#include <cuda_runtime.h>
#include <cuda_bf16.h>
#include <cstdint>

// Shifted-window multi-view attention, v6.
// B=8, M=3, H=W=96, C=128, NS=4 -> 128 windows, L=576, KV=1728.
//  prep_kv: gather K/V per window; K -> bf16 (hi,lo) interleaved uint2;
//           V -> tf32.
//  mv_attn_tc6: QK^T = 3xBF16 m16n8k16 (Qhi*Khi + Qhi*Klo + Qlo*Khi).
//           Qhi fragments resident in registers; Qlo read from smem.
//           PV = tf32 m16n8k8. Fixed-max softmax (P=exp(S), shift-free;
//           scores are O(5)) with per-quad + cross-sub l reduction at end.
// CTA: 256 thr (8 warps), 64 q rows; warp pair owns 16 rows; sub s=warp&1:
// S on kv half (24 rows), PV on channel half (64). KVT=48. 3 syncs/tile.

#define NT 256
#define KVT 48
#define NWIN 128
#define KVLEN 1728

__device__ uint2 g_Khl[(size_t)NWIN * KVLEN * 64];   // (hi,lo) bf16x2 per 2ch
__device__ float g_Vt [(size_t)NWIN * KVLEN * 128];  // tf32

// smem word offsets
#define KHL_W   0          // uint2[48*64]            = 6144 words
#define VS_W    6144       // f32 [48][128]           = 6144 words (Qhi stage in prologue)
#define QLO_W   12288      // u32 [64][64]            = 4096 words
#define PB_W    16384      // f32 [64][52]            = 3328 words
#define SMB_W   19712      // f32 [2][64]             = 128 words
#define REGK_W  19840      // char[1728]              = 432 words
#define SMEM_BYTES ((19840 + 432) * 4)   // 81088
#define P_PITCH 52

__device__ __forceinline__ uint32_t f2tf(float x) {
    uint32_t r; asm("cvt.rna.tf32.f32 %0, %1;" : "=r"(r) : "f"(x)); return r;
}
__device__ __forceinline__ uint32_t bfbits(__nv_bfloat162 h) {
    return *reinterpret_cast<uint32_t*>(&h);
}
__device__ __forceinline__ void mma16(float c[4],
    uint32_t a0, uint32_t a1, uint32_t a2, uint32_t a3, uint32_t b0, uint32_t b1) {
    asm volatile("mma.sync.aligned.m16n8k16.row.col.f32.bf16.bf16.f32 "
        "{%0,%1,%2,%3},{%4,%5,%6,%7},{%8,%9},{%0,%1,%2,%3};"
        : "+f"(c[0]), "+f"(c[1]), "+f"(c[2]), "+f"(c[3])
        : "r"(a0), "r"(a1), "r"(a2), "r"(a3), "r"(b0), "r"(b1));
}
__device__ __forceinline__ void mma8(float c[4],
    uint32_t a0, uint32_t a1, uint32_t a2, uint32_t a3, uint32_t b0, uint32_t b1) {
    asm volatile("mma.sync.aligned.m16n8k8.row.col.f32.tf32.tf32.f32 "
        "{%0,%1,%2,%3},{%4,%5,%6,%7},{%8,%9},{%0,%1,%2,%3};"
        : "+f"(c[0]), "+f"(c[1]), "+f"(c[2]), "+f"(c[3])
        : "r"(a0), "r"(a1), "r"(a2), "r"(a3), "r"(b0), "r"(b1));
}
__device__ __forceinline__ int reg1(int x) { return (x < 72) ? 0 : ((x < 84) ? 1 : 2); }

// ============ prep: gather + convert K/V ============
extern "C" __global__ void __launch_bounds__(256)
prep_kv(const float* __restrict__ kg, const float* __restrict__ vg)
{
    int g = blockIdx.x * 256 + threadIdx.x;     // 0 .. 128*1728*32-1
    int win = g / 55296;
    int rem = g - win * 55296;
    int kv  = rem >> 5;
    int c4  = (rem & 31) << 2;
    int b = win >> 4, sh = (win >> 2) & 3, sw = win & 3;
    int l = kv / 3, mm = kv - 3 * l;
    int i = l / 24, j = l - 24 * i;
    int grow = (sh * 24 + i + 12) % 96;
    int gcol = (sw * 24 + j + 12) % 96;
    size_t src = (((size_t)((b * 3 + mm) * 9216 + grow * 96 + gcol)) << 7) + c4;

    float4 kf = *(const float4*)(kg + src);
    __nv_bfloat162 h0 = __floats2bfloat162_rn(kf.x, kf.y);
    __nv_bfloat162 h1 = __floats2bfloat162_rn(kf.z, kf.w);
    __nv_bfloat162 e0 = __floats2bfloat162_rn(kf.x - __low2float(h0),
                                              kf.y - __high2float(h0));
    __nv_bfloat162 e1 = __floats2bfloat162_rn(kf.z - __low2float(h1),
                                              kf.w - __high2float(h1));
    size_t dst = (size_t)win * (KVLEN * 64) + (size_t)kv * 64 + (c4 >> 1);
    *(uint4*)(g_Khl + dst) = make_uint4(bfbits(h0), bfbits(e0), bfbits(h1), bfbits(e1));

    float4 vf = *(const float4*)(vg + src);
    size_t dv = (size_t)win * (KVLEN * 128) + (size_t)kv * 128 + c4;
    *(uint4*)(g_Vt + dv) = make_uint4(f2tf(vf.x), f2tf(vf.y), f2tf(vf.z), f2tf(vf.w));
}

// ============ main attention kernel ============
extern "C" __global__ void __launch_bounds__(NT, 2)
mv_attn_tc6(const float* __restrict__ qg, float* __restrict__ outg)
{
    extern __shared__ float smem[];
    uint2*    KhlS = (uint2*)smem;               // [48][64]
    float*    Vs   = smem + VS_W;                // [48][128]
    uint32_t* QhiT = (uint32_t*)(smem + VS_W);   // transient Qhi stage (prologue)
    uint32_t* QloS = (uint32_t*)(smem + QLO_W);  // [64][64]
    float*    Pb   = smem + PB_W;                // [64][52]
    float*    SMB  = smem + SMB_W;               // [2][64]
    char*     regK = (char*)(smem + REGK_W);

    const int tid  = threadIdx.x;
    const int warp = tid >> 5;
    const int lane = tid & 31;
    const int gr   = lane >> 2;
    const int tig  = lane & 3;
    const int pair = warp >> 1;
    const int s    = warp & 1;
    const int woff = pair << 4;

    const int win = blockIdx.y;
    const int b   = win >> 4;
    const int sh  = (win >> 2) & 3;
    const int sw  = win & 3;
    const int q0  = blockIdx.x << 6;

    const float scale = 0.08838834764831845f;   // 1/sqrt(128)
    const size_t wb64  = (size_t)win * (KVLEN * 64);
    const size_t wb128 = (size_t)win * (KVLEN * 128);

    // ---- region LUT (tile() quirk: mask column = kv % 576) ----
    for (int idx = tid; idx < KVLEN; idx += NT) {
        int kcol = idx % 576;
        int i = kcol / 24, j = kcol - 24 * i;
        regK[idx] = (char)(reg1(sh * 24 + i) * 3 + reg1(sw * 24 + j));
    }

    // ---- cooperative Q load: gather+scale, split to bf16 hi/lo in smem ----
    #pragma unroll
    for (int it = 0; it < 8; ++it) {
        int idx = tid + it * NT;           // 0..2047
        int r   = idx >> 5;                // 0..63
        int c4  = (idx & 31) << 2;
        int ql  = q0 + r;
        int i = ql / 24, j = ql - 24 * i;
        int grow = (sh * 24 + i + 12) % 96;
        int gcol = (sw * 24 + j + 12) % 96;
        float4 f = *(const float4*)(qg + ((size_t)(b * 9216 + grow * 96 + gcol) << 7) + c4);
        f.x *= scale; f.y *= scale; f.z *= scale; f.w *= scale;
        __nv_bfloat162 h0 = __floats2bfloat162_rn(f.x, f.y);
        __nv_bfloat162 h1 = __floats2bfloat162_rn(f.z, f.w);
        __nv_bfloat162 e0 = __floats2bfloat162_rn(f.x - __low2float(h0),
                                                  f.y - __high2float(h0));
        __nv_bfloat162 e1 = __floats2bfloat162_rn(f.z - __low2float(h1),
                                                  f.w - __high2float(h1));
        int ps = (c4 >> 1) ^ ((r & 7) << 2);
        *(uint2*)&QhiT[r * 64 + ps] = make_uint2(bfbits(h0), bfbits(h1));
        *(uint2*)&QloS[r * 64 + ps] = make_uint2(bfbits(e0), bfbits(e1));
    }
    __syncthreads();

    // ---- Qhi fragments -> registers (persist across all KV tiles) ----
    uint32_t Qh[8][4];
    {
        const int sA = gr << 2;
        #pragma unroll
        for (int st = 0; st < 8; ++st) {
            int pp  = (st << 3) + tig;
            int pA0 = pp ^ sA;
            int pA1 = (pp + 4) ^ sA;
            Qh[st][0] = QhiT[(woff + gr) * 64 + pA0];
            Qh[st][1] = QhiT[(woff + gr + 8) * 64 + pA0];
            Qh[st][2] = QhiT[(woff + gr) * 64 + pA1];
            Qh[st][3] = QhiT[(woff + gr + 8) * 64 + pA1];
        }
    }

    int rq0, rq1;
    {
        int ql = q0 + woff + gr;
        int i = ql / 24, j = ql - 24 * i;
        rq0 = reg1(sh * 24 + i) * 3 + reg1(sw * 24 + j);
        ql += 8; i = ql / 24; j = ql - 24 * i;
        rq1 = reg1(sh * 24 + i) * 3 + reg1(sw * 24 + j);
    }

    float O[8][4];
    #pragma unroll
    for (int nt = 0; nt < 8; ++nt)
        #pragma unroll
        for (int v = 0; v < 4; ++v) O[nt][v] = 0.0f;
    float l0s = 0.0f, l1s = 0.0f;

    const int kvsub = s * 24;      // kv half for S
    const int cbase = s << 6;      // channel half for PV

    for (int kv0 = 0; kv0 < KVLEN; kv0 += KVT) {
        __syncthreads();   // prior readers of KhlS/Vs/Pb (and QhiT on iter 0) done

        // ---- K tile: 48 rows x 32 uint4 ----
        #pragma unroll
        for (int it = 0; it < 6; ++it) {
            int idx = tid + it * NT;            // 0..1535
            int r   = idx >> 5;                 // 0..47
            int p   = (idx & 31) << 1;          // even uint2 position
            int pk  = p ^ ((r & 7) << 2);
            *(uint4*)&KhlS[r * 64 + pk] =
                *(const uint4*)(g_Khl + wb64 + (size_t)(kv0 + r) * 64 + p);
        }
        // ---- V tile: 48 rows x 32 float4 ----
        #pragma unroll
        for (int it = 0; it < 6; ++it) {
            int idx = tid + it * NT;
            int r   = idx >> 5;
            int c4  = (idx & 31) << 2;
            int cv  = c4 ^ ((r & 3) << 3);
            *(float4*)&Vs[r * 128 + cv] =
                *(const float4*)(g_Vt + wb128 + (size_t)(kv0 + r) * 128 + c4);
        }
        __syncthreads();

        // ---- S = Q K^T (3xBF16) ----
        float S[3][4];
        #pragma unroll
        for (int nt = 0; nt < 3; ++nt)
            #pragma unroll
            for (int v = 0; v < 4; ++v) S[nt][v] = 0.0f;

        const int sA = gr << 2;
        #pragma unroll
        for (int st = 0; st < 8; ++st) {
            int pp  = (st << 3) + tig;
            int pA0 = pp ^ sA;
            int pA1 = (pp + 4) ^ sA;
            uint32_t al0 = QloS[(woff + gr) * 64 + pA0];
            uint32_t al1 = QloS[(woff + gr + 8) * 64 + pA0];
            uint32_t al2 = QloS[(woff + gr) * 64 + pA1];
            uint32_t al3 = QloS[(woff + gr + 8) * 64 + pA1];
            #pragma unroll
            for (int nt = 0; nt < 3; ++nt) {
                int kvr = kvsub + (nt << 3) + gr;       // (kvr&7)==gr
                uint2 b0 = KhlS[kvr * 64 + pA0];
                uint2 b1 = KhlS[kvr * 64 + pA1];
                mma16(S[nt], Qh[st][0], Qh[st][1], Qh[st][2], Qh[st][3], b0.x, b1.x);
                mma16(S[nt], Qh[st][0], Qh[st][1], Qh[st][2], Qh[st][3], b0.y, b1.y);
                mma16(S[nt], al0, al1, al2, al3, b0.x, b1.x);
            }
        }

        // ---- mask + exp (fixed-max) + stage P + local l ----
        #pragma unroll
        for (int nt = 0; nt < 3; ++nt) {
            int kvb = kv0 + kvsub + (nt << 3) + (tig << 1);
            int rk0 = regK[kvb], rk1 = regK[kvb + 1];
            float p0 = __expf(rq0 != rk0 ? S[nt][0] - 100.0f : S[nt][0]);
            float p1 = __expf(rq0 != rk1 ? S[nt][1] - 100.0f : S[nt][1]);
            float p2 = __expf(rq1 != rk0 ? S[nt][2] - 100.0f : S[nt][2]);
            float p3 = __expf(rq1 != rk1 ? S[nt][3] - 100.0f : S[nt][3]);
            l0s += p0 + p1;
            l1s += p2 + p3;
            int c = kvsub + (nt << 3) + (tig << 1);
            uint32_t* pr0 = (uint32_t*)&Pb[(woff + gr) * P_PITCH + c];
            uint32_t* pr1 = (uint32_t*)&Pb[(woff + gr + 8) * P_PITCH + c];
            pr0[0] = f2tf(p0); pr0[1] = f2tf(p1);
            pr1[0] = f2tf(p2); pr1[1] = f2tf(p3);
        }
        __syncthreads();   // P complete (both kv halves) before PV reads

        // ---- O += P @ V (tf32) on this warp's 64 channels ----
        const float* Pw = Pb + woff * P_PITCH;
        #pragma unroll
        for (int k8 = 0; k8 < KVT; k8 += 8) {
            uint32_t pa0 = __float_as_uint(Pw[gr * P_PITCH + k8 + tig]);
            uint32_t pa1 = __float_as_uint(Pw[(gr + 8) * P_PITCH + k8 + tig]);
            uint32_t pa2 = __float_as_uint(Pw[gr * P_PITCH + k8 + tig + 4]);
            uint32_t pa3 = __float_as_uint(Pw[(gr + 8) * P_PITCH + k8 + tig + 4]);
            int kvr = k8 + tig;
            int swv = (kvr & 3) << 3;
            #pragma unroll
            for (int nt = 0; nt < 8; ++nt) {
                int cv = (cbase + (nt << 3) + gr) ^ swv;
                uint32_t v0 = __float_as_uint(Vs[kvr * 128 + cv]);
                uint32_t v1 = __float_as_uint(Vs[(kvr + 4) * 128 + cv]);
                mma8(O[nt], pa0, pa1, pa2, pa3, v0, v1);
            }
        }
    }

    // ---- l reduction: quad (tig) shuffle, then cross-sub via smem ----
    l0s += __shfl_xor_sync(0xffffffffu, l0s, 1);
    l0s += __shfl_xor_sync(0xffffffffu, l0s, 2);
    l1s += __shfl_xor_sync(0xffffffffu, l1s, 1);
    l1s += __shfl_xor_sync(0xffffffffu, l1s, 2);
    __syncthreads();
    if (tig == 0) {
        SMB[(s << 6) + woff + gr]     = l0s;
        SMB[(s << 6) + woff + gr + 8] = l1s;
    }
    __syncthreads();
    float lt0 = SMB[woff + gr]     + SMB[64 + woff + gr];
    float lt1 = SMB[woff + gr + 8] + SMB[64 + woff + gr + 8];

    // ---- epilogue: normalize + scatter ----
    float inv0 = 1.0f / lt0, inv1 = 1.0f / lt1;
    int ql0 = q0 + woff + gr;
    int i0 = ql0 / 24, j0 = ql0 - 24 * i0;
    int gr0 = (sh * 24 + i0 + 12) % 96, gc0 = (sw * 24 + j0 + 12) % 96;
    int ql1 = ql0 + 8;
    int i1 = ql1 / 24, j1 = ql1 - 24 * i1;
    int gr1 = (sh * 24 + i1 + 12) % 96, gc1 = (sw * 24 + j1 + 12) % 96;
    float* d0 = outg + ((size_t)(b * 9216 + gr0 * 96 + gc0) << 7) + cbase;
    float* d1 = outg + ((size_t)(b * 9216 + gr1 * 96 + gc1) << 7) + cbase;
    #pragma unroll
    for (int nt = 0; nt < 8; ++nt) {
        int c = (nt << 3) + (tig << 1);
        *(float2*)(d0 + c) = make_float2(O[nt][0] * inv0, O[nt][1] * inv0);
        *(float2*)(d1 + c) = make_float2(O[nt][2] * inv1, O[nt][3] * inv1);
    }
}

extern "C" void kernel_launch(void* const* d_in, const int* in_sizes, int n_in,
                              void* d_out, int out_size)
{
    const float* q = (const float*)d_in[0];
    const float* k = (const float*)d_in[1];
    const float* v = (const float*)d_in[2];
    float* out = (float*)d_out;

    prep_kv<<<27648, 256>>>(k, v);

    cudaFuncSetAttribute(mv_attn_tc6,
                         cudaFuncAttributeMaxDynamicSharedMemorySize, SMEM_BYTES);
    dim3 grid(9, 128, 1);
    mv_attn_tc6<<<grid, NT, SMEM_BYTES>>>(q, out);
}

// round 8
// speedup vs baseline: 1.0867x; 1.0867x over previous
#include <cuda_runtime.h>
#include <cuda_bf16.h>
#include <cstdint>

// Shifted-window multi-view attention, v8 (= v4 numerics + fixed-max softmax,
// no persistent Q registers).
// B=8, M=3, H=W=96, C=128, NS=4 -> 128 windows, L=576, KV=1728.
//  prep_kv: gather K/V per window; K -> bf16 (hi,lo) interleaved uint2;
//           V -> tf32.
//  mv_attn_tc8: QK^T = 3xBF16 m16n8k16 (Qhi*Khi + Qhi*Klo + Qlo*Khi), Q hi/lo
//           both in smem. PV = tf32 m16n8k8 (P,V tf32 — bf16 PV fails
//           accuracy: output rows are near-cancelling means). Fixed-max
//           softmax (P = exp(S); scores O(5), shift-invariant), l reduced
//           once at the end (quad shfl + cross-sub smem exchange).
// CTA: 256 thr (8 warps), 64 q rows; warp pair owns 16 rows; sub s=warp&1:
// S on kv half (24 rows), PV on channel half (64). KVT=48. 3 syncs/tile.

#define NT 256
#define KVT 48
#define NWIN 128
#define KVLEN 1728

__device__ uint2 g_Khl[(size_t)NWIN * KVLEN * 64];   // (hi,lo) bf16x2 per 2ch
__device__ float g_Vt [(size_t)NWIN * KVLEN * 128];  // tf32

// smem word offsets
#define QHI_W   0          // u32 [64][64]   = 4096
#define QLO_W   4096       // u32 [64][64]   = 4096
#define KHL_W   8192       // uint2[48*64]   = 6144 words
#define VS_W    14336      // f32 [48][128]  = 6144
#define PB_W    20480      // f32 [64][52]   = 3328
#define SMB_W   23808      // f32 [2][64]    = 128
#define REGK_W  23936      // char[1728]     = 432 words
#define SMEM_BYTES ((23936 + 432) * 4)   // 97472
#define P_PITCH 52

__device__ __forceinline__ uint32_t f2tf(float x) {
    uint32_t r; asm("cvt.rna.tf32.f32 %0, %1;" : "=r"(r) : "f"(x)); return r;
}
__device__ __forceinline__ uint32_t bfbits(__nv_bfloat162 h) {
    return *reinterpret_cast<uint32_t*>(&h);
}
__device__ __forceinline__ void mma16(float c[4],
    uint32_t a0, uint32_t a1, uint32_t a2, uint32_t a3, uint32_t b0, uint32_t b1) {
    asm volatile("mma.sync.aligned.m16n8k16.row.col.f32.bf16.bf16.f32 "
        "{%0,%1,%2,%3},{%4,%5,%6,%7},{%8,%9},{%0,%1,%2,%3};"
        : "+f"(c[0]), "+f"(c[1]), "+f"(c[2]), "+f"(c[3])
        : "r"(a0), "r"(a1), "r"(a2), "r"(a3), "r"(b0), "r"(b1));
}
__device__ __forceinline__ void mma8(float c[4],
    uint32_t a0, uint32_t a1, uint32_t a2, uint32_t a3, uint32_t b0, uint32_t b1) {
    asm volatile("mma.sync.aligned.m16n8k8.row.col.f32.tf32.tf32.f32 "
        "{%0,%1,%2,%3},{%4,%5,%6,%7},{%8,%9},{%0,%1,%2,%3};"
        : "+f"(c[0]), "+f"(c[1]), "+f"(c[2]), "+f"(c[3])
        : "r"(a0), "r"(a1), "r"(a2), "r"(a3), "r"(b0), "r"(b1));
}
__device__ __forceinline__ int reg1(int x) { return (x < 72) ? 0 : ((x < 84) ? 1 : 2); }

// ============ prep: gather + convert K/V ============
extern "C" __global__ void __launch_bounds__(256)
prep_kv(const float* __restrict__ kg, const float* __restrict__ vg)
{
    int g = blockIdx.x * 256 + threadIdx.x;     // 0 .. 128*1728*32-1
    int win = g / 55296;
    int rem = g - win * 55296;
    int kv  = rem >> 5;
    int c4  = (rem & 31) << 2;
    int b = win >> 4, sh = (win >> 2) & 3, sw = win & 3;
    int l = kv / 3, mm = kv - 3 * l;
    int i = l / 24, j = l - 24 * i;
    int grow = (sh * 24 + i + 12) % 96;
    int gcol = (sw * 24 + j + 12) % 96;
    size_t src = (((size_t)((b * 3 + mm) * 9216 + grow * 96 + gcol)) << 7) + c4;

    float4 kf = *(const float4*)(kg + src);
    __nv_bfloat162 h0 = __floats2bfloat162_rn(kf.x, kf.y);
    __nv_bfloat162 h1 = __floats2bfloat162_rn(kf.z, kf.w);
    __nv_bfloat162 e0 = __floats2bfloat162_rn(kf.x - __low2float(h0),
                                              kf.y - __high2float(h0));
    __nv_bfloat162 e1 = __floats2bfloat162_rn(kf.z - __low2float(h1),
                                              kf.w - __high2float(h1));
    size_t dst = (size_t)win * (KVLEN * 64) + (size_t)kv * 64 + (c4 >> 1);
    *(uint4*)(g_Khl + dst) = make_uint4(bfbits(h0), bfbits(e0), bfbits(h1), bfbits(e1));

    float4 vf = *(const float4*)(vg + src);
    size_t dv = (size_t)win * (KVLEN * 128) + (size_t)kv * 128 + c4;
    *(uint4*)(g_Vt + dv) = make_uint4(f2tf(vf.x), f2tf(vf.y), f2tf(vf.z), f2tf(vf.w));
}

// ============ main attention kernel ============
extern "C" __global__ void __launch_bounds__(NT, 2)
mv_attn_tc8(const float* __restrict__ qg, float* __restrict__ outg)
{
    extern __shared__ float smem[];
    uint32_t* QhiS = (uint32_t*)smem + QHI_W;
    uint32_t* QloS = (uint32_t*)smem + QLO_W;
    uint2*    KhlS = (uint2*)(smem + KHL_W);
    float*    Vs   = smem + VS_W;
    float*    Pb   = smem + PB_W;
    float*    SMB  = smem + SMB_W;
    char*     regK = (char*)(smem + REGK_W);

    const int tid  = threadIdx.x;
    const int warp = tid >> 5;
    const int lane = tid & 31;
    const int gr   = lane >> 2;
    const int tig  = lane & 3;
    const int pair = warp >> 1;
    const int s    = warp & 1;
    const int woff = pair << 4;

    const int win = blockIdx.y;
    const int b   = win >> 4;
    const int sh  = (win >> 2) & 3;
    const int sw  = win & 3;
    const int q0  = blockIdx.x << 6;

    const float scale = 0.08838834764831845f;   // 1/sqrt(128)
    const size_t wb64  = (size_t)win * (KVLEN * 64);
    const size_t wb128 = (size_t)win * (KVLEN * 128);

    // ---- region LUT (tile() quirk: mask column = kv % 576) ----
    for (int idx = tid; idx < KVLEN; idx += NT) {
        int kcol = idx % 576;
        int i = kcol / 24, j = kcol - 24 * i;
        regK[idx] = (char)(reg1(sh * 24 + i) * 3 + reg1(sw * 24 + j));
    }

    // ---- Q: gather + scale + bf16 hi/lo split into smem ----
    #pragma unroll
    for (int it = 0; it < 8; ++it) {
        int idx = tid + it * NT;           // 0..2047
        int r   = idx >> 5;                // 0..63
        int c4  = (idx & 31) << 2;
        int ql  = q0 + r;
        int i = ql / 24, j = ql - 24 * i;
        int grow = (sh * 24 + i + 12) % 96;
        int gcol = (sw * 24 + j + 12) % 96;
        float4 f = *(const float4*)(qg + ((size_t)(b * 9216 + grow * 96 + gcol) << 7) + c4);
        f.x *= scale; f.y *= scale; f.z *= scale; f.w *= scale;
        __nv_bfloat162 h0 = __floats2bfloat162_rn(f.x, f.y);
        __nv_bfloat162 h1 = __floats2bfloat162_rn(f.z, f.w);
        __nv_bfloat162 e0 = __floats2bfloat162_rn(f.x - __low2float(h0),
                                                  f.y - __high2float(h0));
        __nv_bfloat162 e1 = __floats2bfloat162_rn(f.z - __low2float(h1),
                                                  f.w - __high2float(h1));
        int ps = (c4 >> 1) ^ ((r & 7) << 2);
        *(uint2*)&QhiS[r * 64 + ps] = make_uint2(bfbits(h0), bfbits(h1));
        *(uint2*)&QloS[r * 64 + ps] = make_uint2(bfbits(e0), bfbits(e1));
    }

    int rq0, rq1;
    {
        int ql = q0 + woff + gr;
        int i = ql / 24, j = ql - 24 * i;
        rq0 = reg1(sh * 24 + i) * 3 + reg1(sw * 24 + j);
        ql += 8; i = ql / 24; j = ql - 24 * i;
        rq1 = reg1(sh * 24 + i) * 3 + reg1(sw * 24 + j);
    }

    float O[8][4];
    #pragma unroll
    for (int nt = 0; nt < 8; ++nt)
        #pragma unroll
        for (int v = 0; v < 4; ++v) O[nt][v] = 0.0f;
    float l0s = 0.0f, l1s = 0.0f;

    const int kvsub = s * 24;      // kv half for S
    const int cbase = s << 6;      // channel half for PV

    for (int kv0 = 0; kv0 < KVLEN; kv0 += KVT) {
        __syncthreads();   // prior readers of KhlS/Vs/Pb (and Q writes, iter 0) done

        // ---- K tile: 48 rows x 32 uint4 ----
        #pragma unroll
        for (int it = 0; it < 6; ++it) {
            int idx = tid + it * NT;            // 0..1535
            int r   = idx >> 5;                 // 0..47
            int p   = (idx & 31) << 1;          // even uint2 position
            int pk  = p ^ ((r & 7) << 2);
            *(uint4*)&KhlS[r * 64 + pk] =
                *(const uint4*)(g_Khl + wb64 + (size_t)(kv0 + r) * 64 + p);
        }
        // ---- V tile: 48 rows x 32 float4 ----
        #pragma unroll
        for (int it = 0; it < 6; ++it) {
            int idx = tid + it * NT;
            int r   = idx >> 5;
            int c4  = (idx & 31) << 2;
            int cv  = c4 ^ ((r & 3) << 3);
            *(float4*)&Vs[r * 128 + cv] =
                *(const float4*)(g_Vt + wb128 + (size_t)(kv0 + r) * 128 + c4);
        }
        __syncthreads();

        // ---- S = Q K^T (3xBF16) ----
        float S[3][4];
        #pragma unroll
        for (int nt = 0; nt < 3; ++nt)
            #pragma unroll
            for (int v = 0; v < 4; ++v) S[nt][v] = 0.0f;

        const int sA = gr << 2;
        #pragma unroll
        for (int st = 0; st < 8; ++st) {
            int pp  = (st << 3) + tig;
            int pA0 = pp ^ sA;
            int pA1 = (pp + 4) ^ sA;
            uint32_t ah0 = QhiS[(woff + gr) * 64 + pA0];
            uint32_t ah1 = QhiS[(woff + gr + 8) * 64 + pA0];
            uint32_t ah2 = QhiS[(woff + gr) * 64 + pA1];
            uint32_t ah3 = QhiS[(woff + gr + 8) * 64 + pA1];
            uint32_t al0 = QloS[(woff + gr) * 64 + pA0];
            uint32_t al1 = QloS[(woff + gr + 8) * 64 + pA0];
            uint32_t al2 = QloS[(woff + gr) * 64 + pA1];
            uint32_t al3 = QloS[(woff + gr + 8) * 64 + pA1];
            #pragma unroll
            for (int nt = 0; nt < 3; ++nt) {
                int kvr = kvsub + (nt << 3) + gr;       // (kvr&7)==gr
                uint2 b0 = KhlS[kvr * 64 + pA0];
                uint2 b1 = KhlS[kvr * 64 + pA1];
                mma16(S[nt], ah0, ah1, ah2, ah3, b0.x, b1.x);
                mma16(S[nt], ah0, ah1, ah2, ah3, b0.y, b1.y);
                mma16(S[nt], al0, al1, al2, al3, b0.x, b1.x);
            }
        }

        // ---- mask + exp (fixed-max) + stage P (tf32) + local l ----
        #pragma unroll
        for (int nt = 0; nt < 3; ++nt) {
            int kvb = kv0 + kvsub + (nt << 3) + (tig << 1);
            int rk0 = regK[kvb], rk1 = regK[kvb + 1];
            float p0 = __expf(rq0 != rk0 ? S[nt][0] - 100.0f : S[nt][0]);
            float p1 = __expf(rq0 != rk1 ? S[nt][1] - 100.0f : S[nt][1]);
            float p2 = __expf(rq1 != rk0 ? S[nt][2] - 100.0f : S[nt][2]);
            float p3 = __expf(rq1 != rk1 ? S[nt][3] - 100.0f : S[nt][3]);
            l0s += p0 + p1;
            l1s += p2 + p3;
            int c = kvsub + (nt << 3) + (tig << 1);
            uint32_t* pr0 = (uint32_t*)&Pb[(woff + gr) * P_PITCH + c];
            uint32_t* pr1 = (uint32_t*)&Pb[(woff + gr + 8) * P_PITCH + c];
            pr0[0] = f2tf(p0); pr0[1] = f2tf(p1);
            pr1[0] = f2tf(p2); pr1[1] = f2tf(p3);
        }
        __syncthreads();   // P complete (both kv halves) before PV reads

        // ---- O += P @ V (tf32) on this warp's 64 channels ----
        const float* Pw = Pb + woff * P_PITCH;
        #pragma unroll
        for (int k8 = 0; k8 < KVT; k8 += 8) {
            uint32_t pa0 = __float_as_uint(Pw[gr * P_PITCH + k8 + tig]);
            uint32_t pa1 = __float_as_uint(Pw[(gr + 8) * P_PITCH + k8 + tig]);
            uint32_t pa2 = __float_as_uint(Pw[gr * P_PITCH + k8 + tig + 4]);
            uint32_t pa3 = __float_as_uint(Pw[(gr + 8) * P_PITCH + k8 + tig + 4]);
            int kvr = k8 + tig;
            int swv = (kvr & 3) << 3;
            #pragma unroll
            for (int nt = 0; nt < 8; ++nt) {
                int cv = (cbase + (nt << 3) + gr) ^ swv;
                uint32_t v0 = __float_as_uint(Vs[kvr * 128 + cv]);
                uint32_t v1 = __float_as_uint(Vs[(kvr + 4) * 128 + cv]);
                mma8(O[nt], pa0, pa1, pa2, pa3, v0, v1);
            }
        }
    }

    // ---- l reduction: quad shuffle, then cross-sub via smem ----
    l0s += __shfl_xor_sync(0xffffffffu, l0s, 1);
    l0s += __shfl_xor_sync(0xffffffffu, l0s, 2);
    l1s += __shfl_xor_sync(0xffffffffu, l1s, 1);
    l1s += __shfl_xor_sync(0xffffffffu, l1s, 2);
    __syncthreads();
    if (tig == 0) {
        SMB[(s << 6) + woff + gr]     = l0s;
        SMB[(s << 6) + woff + gr + 8] = l1s;
    }
    __syncthreads();
    float lt0 = SMB[woff + gr]     + SMB[64 + woff + gr];
    float lt1 = SMB[woff + gr + 8] + SMB[64 + woff + gr + 8];

    // ---- epilogue: normalize + scatter ----
    float inv0 = 1.0f / lt0, inv1 = 1.0f / lt1;
    int ql0 = q0 + woff + gr;
    int i0 = ql0 / 24, j0 = ql0 - 24 * i0;
    int gr0 = (sh * 24 + i0 + 12) % 96, gc0 = (sw * 24 + j0 + 12) % 96;
    int ql1 = ql0 + 8;
    int i1 = ql1 / 24, j1 = ql1 - 24 * i1;
    int gr1 = (sh * 24 + i1 + 12) % 96, gc1 = (sw * 24 + j1 + 12) % 96;
    float* d0 = outg + ((size_t)(b * 9216 + gr0 * 96 + gc0) << 7) + cbase;
    float* d1 = outg + ((size_t)(b * 9216 + gr1 * 96 + gc1) << 7) + cbase;
    #pragma unroll
    for (int nt = 0; nt < 8; ++nt) {
        int c = (nt << 3) + (tig << 1);
        *(float2*)(d0 + c) = make_float2(O[nt][0] * inv0, O[nt][1] * inv0);
        *(float2*)(d1 + c) = make_float2(O[nt][2] * inv1, O[nt][3] * inv1);
    }
}

extern "C" void kernel_launch(void* const* d_in, const int* in_sizes, int n_in,
                              void* d_out, int out_size)
{
    const float* q = (const float*)d_in[0];
    const float* k = (const float*)d_in[1];
    const float* v = (const float*)d_in[2];
    float* out = (float*)d_out;

    prep_kv<<<27648, 256>>>(k, v);

    cudaFuncSetAttribute(mv_attn_tc8,
                         cudaFuncAttributeMaxDynamicSharedMemorySize, SMEM_BYTES);
    dim3 grid(9, 128, 1);
    mv_attn_tc8<<<grid, NT, SMEM_BYTES>>>(q, out);
}

// round 9
// speedup vs baseline: 1.1064x; 1.0182x over previous
#include <cuda_runtime.h>
#include <cuda_bf16.h>
#include <cstdint>

// Shifted-window multi-view attention, v9 = v8 numerics + cp.async
// double-buffered KV pipeline + named-barrier P exchange.
// B=8, M=3, H=W=96, C=128, NS=4 -> 128 windows, L=576, KV=1728.
//  prep_kv: gather K/V per window; K -> bf16 (hi,lo) interleaved uint2;
//           V -> tf32.
//  mv_attn_tc9: QK^T = 3xBF16 m16n8k16 (Qhi*Khi+Qhi*Klo+Qlo*Khi), Q in smem.
//           PV = tf32 m16n8k8. Fixed-max softmax; l reduced once at end.
//           KV tiles (KVT=32) double-buffered via cp.async: prefetch tile
//           i+1 during compute of tile i. One __syncthreads per tile +
//           one named barrier per warp-pair for the P handoff.
// CTA: 256 thr (8 warps), 64 q rows; warp pair owns 16 rows; sub s=warp&1:
// S on kv half (16 rows), PV on channel half (64).

#define NT 256
#define KVT 32
#define NTILES 54              // 1728 / 32
#define NWIN 128
#define KVLEN 1728

__device__ uint2 g_Khl[(size_t)NWIN * KVLEN * 64];   // (hi,lo) bf16x2 per 2ch
__device__ float g_Vt [(size_t)NWIN * KVLEN * 128];  // tf32

// smem word offsets
#define QHI_W   0          // u32 [64][64]           4096
#define QLO_W   4096       // u32 [64][64]           4096
#define KHL_W   8192       // uint2[2][32*64]        8192 words
#define VS_W    16384      // f32 [2][32][128]       8192
#define PB_W    24576      // f32 [64][36]           2304
#define SMB_W   26880      // f32 [2][64]            128
#define REGK_W  27008      // char[1728]             432 words
#define SMEM_BYTES (27440 * 4)   // 109760
#define P_PITCH 36

__device__ __forceinline__ uint32_t f2tf(float x) {
    uint32_t r; asm("cvt.rna.tf32.f32 %0, %1;" : "=r"(r) : "f"(x)); return r;
}
__device__ __forceinline__ uint32_t bfbits(__nv_bfloat162 h) {
    return *reinterpret_cast<uint32_t*>(&h);
}
__device__ __forceinline__ void cp16(uint32_t dst, const void* src) {
    asm volatile("cp.async.cg.shared.global [%0], [%1], 16;" :: "r"(dst), "l"(src));
}
__device__ __forceinline__ void cp_commit() {
    asm volatile("cp.async.commit_group;" ::: "memory");
}
__device__ __forceinline__ void cp_wait_all() {
    asm volatile("cp.async.wait_group 0;" ::: "memory");
}
__device__ __forceinline__ void mma16(float c[4],
    uint32_t a0, uint32_t a1, uint32_t a2, uint32_t a3, uint32_t b0, uint32_t b1) {
    asm volatile("mma.sync.aligned.m16n8k16.row.col.f32.bf16.bf16.f32 "
        "{%0,%1,%2,%3},{%4,%5,%6,%7},{%8,%9},{%0,%1,%2,%3};"
        : "+f"(c[0]), "+f"(c[1]), "+f"(c[2]), "+f"(c[3])
        : "r"(a0), "r"(a1), "r"(a2), "r"(a3), "r"(b0), "r"(b1));
}
__device__ __forceinline__ void mma8(float c[4],
    uint32_t a0, uint32_t a1, uint32_t a2, uint32_t a3, uint32_t b0, uint32_t b1) {
    asm volatile("mma.sync.aligned.m16n8k8.row.col.f32.tf32.tf32.f32 "
        "{%0,%1,%2,%3},{%4,%5,%6,%7},{%8,%9},{%0,%1,%2,%3};"
        : "+f"(c[0]), "+f"(c[1]), "+f"(c[2]), "+f"(c[3])
        : "r"(a0), "r"(a1), "r"(a2), "r"(a3), "r"(b0), "r"(b1));
}
__device__ __forceinline__ int reg1(int x) { return (x < 72) ? 0 : ((x < 84) ? 1 : 2); }

// ============ prep: gather + convert K/V ============
extern "C" __global__ void __launch_bounds__(256)
prep_kv(const float* __restrict__ kg, const float* __restrict__ vg)
{
    int g = blockIdx.x * 256 + threadIdx.x;     // 0 .. 128*1728*32-1
    int win = g / 55296;
    int rem = g - win * 55296;
    int kv  = rem >> 5;
    int c4  = (rem & 31) << 2;
    int b = win >> 4, sh = (win >> 2) & 3, sw = win & 3;
    int l = kv / 3, mm = kv - 3 * l;
    int i = l / 24, j = l - 24 * i;
    int grow = (sh * 24 + i + 12) % 96;
    int gcol = (sw * 24 + j + 12) % 96;
    size_t src = (((size_t)((b * 3 + mm) * 9216 + grow * 96 + gcol)) << 7) + c4;

    float4 kf = *(const float4*)(kg + src);
    __nv_bfloat162 h0 = __floats2bfloat162_rn(kf.x, kf.y);
    __nv_bfloat162 h1 = __floats2bfloat162_rn(kf.z, kf.w);
    __nv_bfloat162 e0 = __floats2bfloat162_rn(kf.x - __low2float(h0),
                                              kf.y - __high2float(h0));
    __nv_bfloat162 e1 = __floats2bfloat162_rn(kf.z - __low2float(h1),
                                              kf.w - __high2float(h1));
    size_t dst = (size_t)win * (KVLEN * 64) + (size_t)kv * 64 + (c4 >> 1);
    *(uint4*)(g_Khl + dst) = make_uint4(bfbits(h0), bfbits(e0), bfbits(h1), bfbits(e1));

    float4 vf = *(const float4*)(vg + src);
    size_t dv = (size_t)win * (KVLEN * 128) + (size_t)kv * 128 + c4;
    *(uint4*)(g_Vt + dv) = make_uint4(f2tf(vf.x), f2tf(vf.y), f2tf(vf.z), f2tf(vf.w));
}

// ============ main attention kernel ============
extern "C" __global__ void __launch_bounds__(NT, 2)
mv_attn_tc9(const float* __restrict__ qg, float* __restrict__ outg)
{
    extern __shared__ float smem[];
    uint32_t* QhiS = (uint32_t*)smem + QHI_W;
    uint32_t* QloS = (uint32_t*)smem + QLO_W;
    float*    Pb   = smem + PB_W;
    float*    SMB  = smem + SMB_W;
    char*     regK = (char*)(smem + REGK_W);
    const uint32_t smem_u32 = (uint32_t)__cvta_generic_to_shared(smem);
    const uint32_t khl_b    = smem_u32 + KHL_W * 4;   // byte addr of K ring
    const uint32_t vs_b     = smem_u32 + VS_W * 4;    // byte addr of V ring

    const int tid  = threadIdx.x;
    const int warp = tid >> 5;
    const int lane = tid & 31;
    const int gr   = lane >> 2;
    const int tig  = lane & 3;
    const int pair = warp >> 1;
    const int s    = warp & 1;
    const int woff = pair << 4;

    const int win = blockIdx.y;
    const int b   = win >> 4;
    const int sh  = (win >> 2) & 3;
    const int sw  = win & 3;
    const int q0  = blockIdx.x << 6;

    const float scale = 0.08838834764831845f;   // 1/sqrt(128)
    const size_t wb64  = (size_t)win * (KVLEN * 64);
    const size_t wb128 = (size_t)win * (KVLEN * 128);

    // per-thread cp.async slot assignments (4 K + 4 V per tile)
    const int kr  = tid >> 3;                 // 0..31  K row
    const int kp  = (tid & 7) << 3;           // uint2 pos 0,8,..,56 (this thread does 4 of 8)
    const int vr  = tid >> 3;                 // 0..31  V row
    const int vc  = (tid & 7) << 4;           // f32 col (this thread does 4 float4 of row half)

    // ---- region LUT (tile() quirk: mask column = kv % 576) ----
    for (int idx = tid; idx < KVLEN; idx += NT) {
        int kcol = idx % 576;
        int i = kcol / 24, j = kcol - 24 * i;
        regK[idx] = (char)(reg1(sh * 24 + i) * 3 + reg1(sw * 24 + j));
    }

    // ---- prefetch tile 0 into buffer 0 ----
    {
        const uint2* ksrc = g_Khl + wb64 + (size_t)kr * 64;
        #pragma unroll
        for (int u = 0; u < 4; ++u) {
            int p  = kp + (u << 1);
            int pk = p ^ ((kr & 7) << 2);
            cp16(khl_b + (kr * 64 + pk) * 8, ksrc + p);
        }
        const float* vsrc = g_Vt + wb128 + (size_t)vr * 128;
        #pragma unroll
        for (int u = 0; u < 4; ++u) {
            int c4 = vc + (u << 2);
            int cv = c4 ^ ((vr & 3) << 3);
            cp16(vs_b + (vr * 128 + cv) * 4, vsrc + c4);
        }
        cp_commit();
    }

    // ---- Q: gather + scale + bf16 hi/lo split into smem ----
    #pragma unroll
    for (int it = 0; it < 8; ++it) {
        int idx = tid + it * NT;
        int r   = idx >> 5;
        int c4  = (idx & 31) << 2;
        int ql  = q0 + r;
        int i = ql / 24, j = ql - 24 * i;
        int grow = (sh * 24 + i + 12) % 96;
        int gcol = (sw * 24 + j + 12) % 96;
        float4 f = *(const float4*)(qg + ((size_t)(b * 9216 + grow * 96 + gcol) << 7) + c4);
        f.x *= scale; f.y *= scale; f.z *= scale; f.w *= scale;
        __nv_bfloat162 h0 = __floats2bfloat162_rn(f.x, f.y);
        __nv_bfloat162 h1 = __floats2bfloat162_rn(f.z, f.w);
        __nv_bfloat162 e0 = __floats2bfloat162_rn(f.x - __low2float(h0),
                                                  f.y - __high2float(h0));
        __nv_bfloat162 e1 = __floats2bfloat162_rn(f.z - __low2float(h1),
                                                  f.w - __high2float(h1));
        int ps = (c4 >> 1) ^ ((r & 7) << 2);
        *(uint2*)&QhiS[r * 64 + ps] = make_uint2(bfbits(h0), bfbits(h1));
        *(uint2*)&QloS[r * 64 + ps] = make_uint2(bfbits(e0), bfbits(e1));
    }

    int rq0, rq1;
    {
        int ql = q0 + woff + gr;
        int i = ql / 24, j = ql - 24 * i;
        rq0 = reg1(sh * 24 + i) * 3 + reg1(sw * 24 + j);
        ql += 8; i = ql / 24; j = ql - 24 * i;
        rq1 = reg1(sh * 24 + i) * 3 + reg1(sw * 24 + j);
    }

    float O[8][4];
    #pragma unroll
    for (int nt = 0; nt < 8; ++nt)
        #pragma unroll
        for (int v = 0; v < 4; ++v) O[nt][v] = 0.0f;
    float l0s = 0.0f, l1s = 0.0f;

    const int kvsub = s << 4;      // kv half for S (16 rows)
    const int cbase = s << 6;      // channel half for PV
    const int barid = 1 + pair;

    for (int t = 0; t < NTILES; ++t) {
        const int kv0 = t * KVT;
        const int buf = t & 1;
        cp_wait_all();
        __syncthreads();   // tile t resident; all compute on buf^1 (t-1) done

        // ---- prefetch tile t+1 into buf^1 (overlaps with compute below) ----
        if (t + 1 < NTILES) {
            const int nb = buf ^ 1;
            const uint2* ksrc = g_Khl + wb64 + (size_t)(kv0 + KVT + kr) * 64;
            #pragma unroll
            for (int u = 0; u < 4; ++u) {
                int p  = kp + (u << 1);
                int pk = p ^ ((kr & 7) << 2);
                cp16(khl_b + (nb * 2048 + kr * 64 + pk) * 8, ksrc + p);
            }
            const float* vsrc = g_Vt + wb128 + (size_t)(kv0 + KVT + vr) * 128;
            #pragma unroll
            for (int u = 0; u < 4; ++u) {
                int c4 = vc + (u << 2);
                int cv = c4 ^ ((vr & 3) << 3);
                cp16(vs_b + (nb * 4096 + vr * 128 + cv) * 4, vsrc + c4);
            }
            cp_commit();
        }

        const uint2* KhlS = (const uint2*)(smem + KHL_W) + buf * 2048;
        const float* Vs   = smem + VS_W + buf * 4096;

        // ---- S = Q K^T (3xBF16) ----
        float S[2][4];
        #pragma unroll
        for (int nt = 0; nt < 2; ++nt)
            #pragma unroll
            for (int v = 0; v < 4; ++v) S[nt][v] = 0.0f;

        const int sA = gr << 2;
        #pragma unroll
        for (int st = 0; st < 8; ++st) {
            int pp  = (st << 3) + tig;
            int pA0 = pp ^ sA;
            int pA1 = (pp + 4) ^ sA;
            uint32_t ah0 = QhiS[(woff + gr) * 64 + pA0];
            uint32_t ah1 = QhiS[(woff + gr + 8) * 64 + pA0];
            uint32_t ah2 = QhiS[(woff + gr) * 64 + pA1];
            uint32_t ah3 = QhiS[(woff + gr + 8) * 64 + pA1];
            uint32_t al0 = QloS[(woff + gr) * 64 + pA0];
            uint32_t al1 = QloS[(woff + gr + 8) * 64 + pA0];
            uint32_t al2 = QloS[(woff + gr) * 64 + pA1];
            uint32_t al3 = QloS[(woff + gr + 8) * 64 + pA1];
            #pragma unroll
            for (int nt = 0; nt < 2; ++nt) {
                int kvr = kvsub + (nt << 3) + gr;       // (kvr&7)==gr
                uint2 b0 = KhlS[kvr * 64 + pA0];
                uint2 b1 = KhlS[kvr * 64 + pA1];
                mma16(S[nt], ah0, ah1, ah2, ah3, b0.x, b1.x);
                mma16(S[nt], ah0, ah1, ah2, ah3, b0.y, b1.y);
                mma16(S[nt], al0, al1, al2, al3, b0.x, b1.x);
            }
        }

        // ---- mask + exp (fixed-max) + stage P (tf32) + local l ----
        #pragma unroll
        for (int nt = 0; nt < 2; ++nt) {
            int kvb = kv0 + kvsub + (nt << 3) + (tig << 1);
            int rk0 = regK[kvb], rk1 = regK[kvb + 1];
            float p0 = __expf(rq0 != rk0 ? S[nt][0] - 100.0f : S[nt][0]);
            float p1 = __expf(rq0 != rk1 ? S[nt][1] - 100.0f : S[nt][1]);
            float p2 = __expf(rq1 != rk0 ? S[nt][2] - 100.0f : S[nt][2]);
            float p3 = __expf(rq1 != rk1 ? S[nt][3] - 100.0f : S[nt][3]);
            l0s += p0 + p1;
            l1s += p2 + p3;
            int c = kvsub + (nt << 3) + (tig << 1);
            uint32_t* pr0 = (uint32_t*)&Pb[(woff + gr) * P_PITCH + c];
            uint32_t* pr1 = (uint32_t*)&Pb[(woff + gr + 8) * P_PITCH + c];
            pr0[0] = f2tf(p0); pr0[1] = f2tf(p1);
            pr1[0] = f2tf(p2); pr1[1] = f2tf(p3);
        }
        // P handoff is pair-local: both warps of the pair wrote their kv
        // halves of rows woff..woff+15; both read the full 32 kv below.
        asm volatile("bar.sync %0, 64;" :: "r"(barid) : "memory");

        // ---- O += P @ V (tf32) on this warp's 64 channels ----
        const float* Pw = Pb + woff * P_PITCH;
        #pragma unroll
        for (int k8 = 0; k8 < KVT; k8 += 8) {
            uint32_t pa0 = __float_as_uint(Pw[gr * P_PITCH + k8 + tig]);
            uint32_t pa1 = __float_as_uint(Pw[(gr + 8) * P_PITCH + k8 + tig]);
            uint32_t pa2 = __float_as_uint(Pw[gr * P_PITCH + k8 + tig + 4]);
            uint32_t pa3 = __float_as_uint(Pw[(gr + 8) * P_PITCH + k8 + tig + 4]);
            int kvr = k8 + tig;
            int swv = (kvr & 3) << 3;
            #pragma unroll
            for (int nt = 0; nt < 8; ++nt) {
                int cv = (cbase + (nt << 3) + gr) ^ swv;
                uint32_t v0 = __float_as_uint(Vs[kvr * 128 + cv]);
                uint32_t v1 = __float_as_uint(Vs[(kvr + 4) * 128 + cv]);
                mma8(O[nt], pa0, pa1, pa2, pa3, v0, v1);
            }
        }
    }

    // ---- l reduction: quad shuffle, then cross-sub via smem ----
    l0s += __shfl_xor_sync(0xffffffffu, l0s, 1);
    l0s += __shfl_xor_sync(0xffffffffu, l0s, 2);
    l1s += __shfl_xor_sync(0xffffffffu, l1s, 1);
    l1s += __shfl_xor_sync(0xffffffffu, l1s, 2);
    __syncthreads();
    if (tig == 0) {
        SMB[(s << 6) + woff + gr]     = l0s;
        SMB[(s << 6) + woff + gr + 8] = l1s;
    }
    __syncthreads();
    float lt0 = SMB[woff + gr]     + SMB[64 + woff + gr];
    float lt1 = SMB[woff + gr + 8] + SMB[64 + woff + gr + 8];

    // ---- epilogue: normalize + scatter ----
    float inv0 = 1.0f / lt0, inv1 = 1.0f / lt1;
    int ql0 = q0 + woff + gr;
    int i0 = ql0 / 24, j0 = ql0 - 24 * i0;
    int gr0 = (sh * 24 + i0 + 12) % 96, gc0 = (sw * 24 + j0 + 12) % 96;
    int ql1 = ql0 + 8;
    int i1 = ql1 / 24, j1 = ql1 - 24 * i1;
    int gr1 = (sh * 24 + i1 + 12) % 96, gc1 = (sw * 24 + j1 + 12) % 96;
    float* d0 = outg + ((size_t)(b * 9216 + gr0 * 96 + gc0) << 7) + cbase;
    float* d1 = outg + ((size_t)(b * 9216 + gr1 * 96 + gc1) << 7) + cbase;
    #pragma unroll
    for (int nt = 0; nt < 8; ++nt) {
        int c = (nt << 3) + (tig << 1);
        *(float2*)(d0 + c) = make_float2(O[nt][0] * inv0, O[nt][1] * inv0);
        *(float2*)(d1 + c) = make_float2(O[nt][2] * inv1, O[nt][3] * inv1);
    }
}

extern "C" void kernel_launch(void* const* d_in, const int* in_sizes, int n_in,
                              void* d_out, int out_size)
{
    const float* q = (const float*)d_in[0];
    const float* k = (const float*)d_in[1];
    const float* v = (const float*)d_in[2];
    float* out = (float*)d_out;

    prep_kv<<<27648, 256>>>(k, v);

    cudaFuncSetAttribute(mv_attn_tc9,
                         cudaFuncAttributeMaxDynamicSharedMemorySize, SMEM_BYTES);
    dim3 grid(9, 128, 1);
    mv_attn_tc9<<<grid, NT, SMEM_BYTES>>>(q, out);
}

// round 10
// speedup vs baseline: 1.1069x; 1.0004x over previous
#include <cuda_runtime.h>
#include <cuda_bf16.h>
#include <cstdint>

// Shifted-window multi-view attention, v9 = v8 numerics + cp.async
// double-buffered KV pipeline + named-barrier P exchange.
// B=8, M=3, H=W=96, C=128, NS=4 -> 128 windows, L=576, KV=1728.
//  prep_kv: gather K/V per window; K -> bf16 (hi,lo) interleaved uint2;
//           V -> tf32.
//  mv_attn_tc9: QK^T = 3xBF16 m16n8k16 (Qhi*Khi+Qhi*Klo+Qlo*Khi), Q in smem.
//           PV = tf32 m16n8k8. Fixed-max softmax; l reduced once at end.
//           KV tiles (KVT=32) double-buffered via cp.async: prefetch tile
//           i+1 during compute of tile i. One __syncthreads per tile +
//           one named barrier per warp-pair for the P handoff.
// CTA: 256 thr (8 warps), 64 q rows; warp pair owns 16 rows; sub s=warp&1:
// S on kv half (16 rows), PV on channel half (64).

#define NT 256
#define KVT 32
#define NTILES 54              // 1728 / 32
#define NWIN 128
#define KVLEN 1728

__device__ uint2 g_Khl[(size_t)NWIN * KVLEN * 64];   // (hi,lo) bf16x2 per 2ch
__device__ float g_Vt [(size_t)NWIN * KVLEN * 128];  // tf32

// smem word offsets
#define QHI_W   0          // u32 [64][64]           4096
#define QLO_W   4096       // u32 [64][64]           4096
#define KHL_W   8192       // uint2[2][32*64]        8192 words
#define VS_W    16384      // f32 [2][32][128]       8192
#define PB_W    24576      // f32 [64][36]           2304
#define SMB_W   26880      // f32 [2][64]            128
#define REGK_W  27008      // char[1728]             432 words
#define SMEM_BYTES (27440 * 4)   // 109760
#define P_PITCH 36

__device__ __forceinline__ uint32_t f2tf(float x) {
    uint32_t r; asm("cvt.rna.tf32.f32 %0, %1;" : "=r"(r) : "f"(x)); return r;
}
__device__ __forceinline__ uint32_t bfbits(__nv_bfloat162 h) {
    return *reinterpret_cast<uint32_t*>(&h);
}
__device__ __forceinline__ void cp16(uint32_t dst, const void* src) {
    asm volatile("cp.async.cg.shared.global [%0], [%1], 16;" :: "r"(dst), "l"(src));
}
__device__ __forceinline__ void cp_commit() {
    asm volatile("cp.async.commit_group;" ::: "memory");
}
__device__ __forceinline__ void cp_wait_all() {
    asm volatile("cp.async.wait_group 0;" ::: "memory");
}
__device__ __forceinline__ void mma16(float c[4],
    uint32_t a0, uint32_t a1, uint32_t a2, uint32_t a3, uint32_t b0, uint32_t b1) {
    asm volatile("mma.sync.aligned.m16n8k16.row.col.f32.bf16.bf16.f32 "
        "{%0,%1,%2,%3},{%4,%5,%6,%7},{%8,%9},{%0,%1,%2,%3};"
        : "+f"(c[0]), "+f"(c[1]), "+f"(c[2]), "+f"(c[3])
        : "r"(a0), "r"(a1), "r"(a2), "r"(a3), "r"(b0), "r"(b1));
}
__device__ __forceinline__ void mma8(float c[4],
    uint32_t a0, uint32_t a1, uint32_t a2, uint32_t a3, uint32_t b0, uint32_t b1) {
    asm volatile("mma.sync.aligned.m16n8k8.row.col.f32.tf32.tf32.f32 "
        "{%0,%1,%2,%3},{%4,%5,%6,%7},{%8,%9},{%0,%1,%2,%3};"
        : "+f"(c[0]), "+f"(c[1]), "+f"(c[2]), "+f"(c[3])
        : "r"(a0), "r"(a1), "r"(a2), "r"(a3), "r"(b0), "r"(b1));
}
__device__ __forceinline__ int reg1(int x) { return (x < 72) ? 0 : ((x < 84) ? 1 : 2); }

// ============ prep: gather + convert K/V ============
extern "C" __global__ void __launch_bounds__(256)
prep_kv(const float* __restrict__ kg, const float* __restrict__ vg)
{
    int g = blockIdx.x * 256 + threadIdx.x;     // 0 .. 128*1728*32-1
    int win = g / 55296;
    int rem = g - win * 55296;
    int kv  = rem >> 5;
    int c4  = (rem & 31) << 2;
    int b = win >> 4, sh = (win >> 2) & 3, sw = win & 3;
    int l = kv / 3, mm = kv - 3 * l;
    int i = l / 24, j = l - 24 * i;
    int grow = (sh * 24 + i + 12) % 96;
    int gcol = (sw * 24 + j + 12) % 96;
    size_t src = (((size_t)((b * 3 + mm) * 9216 + grow * 96 + gcol)) << 7) + c4;

    float4 kf = *(const float4*)(kg + src);
    __nv_bfloat162 h0 = __floats2bfloat162_rn(kf.x, kf.y);
    __nv_bfloat162 h1 = __floats2bfloat162_rn(kf.z, kf.w);
    __nv_bfloat162 e0 = __floats2bfloat162_rn(kf.x - __low2float(h0),
                                              kf.y - __high2float(h0));
    __nv_bfloat162 e1 = __floats2bfloat162_rn(kf.z - __low2float(h1),
                                              kf.w - __high2float(h1));
    size_t dst = (size_t)win * (KVLEN * 64) + (size_t)kv * 64 + (c4 >> 1);
    *(uint4*)(g_Khl + dst) = make_uint4(bfbits(h0), bfbits(e0), bfbits(h1), bfbits(e1));

    float4 vf = *(const float4*)(vg + src);
    size_t dv = (size_t)win * (KVLEN * 128) + (size_t)kv * 128 + c4;
    *(uint4*)(g_Vt + dv) = make_uint4(f2tf(vf.x), f2tf(vf.y), f2tf(vf.z), f2tf(vf.w));
}

// ============ main attention kernel ============
extern "C" __global__ void __launch_bounds__(NT, 2)
mv_attn_tc9(const float* __restrict__ qg, float* __restrict__ outg)
{
    extern __shared__ float smem[];
    uint32_t* QhiS = (uint32_t*)smem + QHI_W;
    uint32_t* QloS = (uint32_t*)smem + QLO_W;
    float*    Pb   = smem + PB_W;
    float*    SMB  = smem + SMB_W;
    char*     regK = (char*)(smem + REGK_W);
    const uint32_t smem_u32 = (uint32_t)__cvta_generic_to_shared(smem);
    const uint32_t khl_b    = smem_u32 + KHL_W * 4;   // byte addr of K ring
    const uint32_t vs_b     = smem_u32 + VS_W * 4;    // byte addr of V ring

    const int tid  = threadIdx.x;
    const int warp = tid >> 5;
    const int lane = tid & 31;
    const int gr   = lane >> 2;
    const int tig  = lane & 3;
    const int pair = warp >> 1;
    const int s    = warp & 1;
    const int woff = pair << 4;

    const int win = blockIdx.y;
    const int b   = win >> 4;
    const int sh  = (win >> 2) & 3;
    const int sw  = win & 3;
    const int q0  = blockIdx.x << 6;

    const float scale = 0.08838834764831845f;   // 1/sqrt(128)
    const size_t wb64  = (size_t)win * (KVLEN * 64);
    const size_t wb128 = (size_t)win * (KVLEN * 128);

    // per-thread cp.async slot assignments (4 K + 4 V per tile)
    const int kr  = tid >> 3;                 // 0..31  K row
    const int kp  = (tid & 7) << 3;           // uint2 pos 0,8,..,56 (this thread does 4 of 8)
    const int vr  = tid >> 3;                 // 0..31  V row
    const int vc  = (tid & 7) << 4;           // f32 col (this thread does 4 float4 of row half)

    // ---- region LUT (tile() quirk: mask column = kv % 576) ----
    for (int idx = tid; idx < KVLEN; idx += NT) {
        int kcol = idx % 576;
        int i = kcol / 24, j = kcol - 24 * i;
        regK[idx] = (char)(reg1(sh * 24 + i) * 3 + reg1(sw * 24 + j));
    }

    // ---- prefetch tile 0 into buffer 0 ----
    {
        const uint2* ksrc = g_Khl + wb64 + (size_t)kr * 64;
        #pragma unroll
        for (int u = 0; u < 4; ++u) {
            int p  = kp + (u << 1);
            int pk = p ^ ((kr & 7) << 2);
            cp16(khl_b + (kr * 64 + pk) * 8, ksrc + p);
        }
        const float* vsrc = g_Vt + wb128 + (size_t)vr * 128;
        #pragma unroll
        for (int u = 0; u < 4; ++u) {
            int c4 = vc + (u << 2);
            int cv = c4 ^ ((vr & 3) << 3);
            cp16(vs_b + (vr * 128 + cv) * 4, vsrc + c4);
        }
        cp_commit();
    }

    // ---- Q: gather + scale + bf16 hi/lo split into smem ----
    #pragma unroll
    for (int it = 0; it < 8; ++it) {
        int idx = tid + it * NT;
        int r   = idx >> 5;
        int c4  = (idx & 31) << 2;
        int ql  = q0 + r;
        int i = ql / 24, j = ql - 24 * i;
        int grow = (sh * 24 + i + 12) % 96;
        int gcol = (sw * 24 + j + 12) % 96;
        float4 f = *(const float4*)(qg + ((size_t)(b * 9216 + grow * 96 + gcol) << 7) + c4);
        f.x *= scale; f.y *= scale; f.z *= scale; f.w *= scale;
        __nv_bfloat162 h0 = __floats2bfloat162_rn(f.x, f.y);
        __nv_bfloat162 h1 = __floats2bfloat162_rn(f.z, f.w);
        __nv_bfloat162 e0 = __floats2bfloat162_rn(f.x - __low2float(h0),
                                                  f.y - __high2float(h0));
        __nv_bfloat162 e1 = __floats2bfloat162_rn(f.z - __low2float(h1),
                                                  f.w - __high2float(h1));
        int ps = (c4 >> 1) ^ ((r & 7) << 2);
        *(uint2*)&QhiS[r * 64 + ps] = make_uint2(bfbits(h0), bfbits(h1));
        *(uint2*)&QloS[r * 64 + ps] = make_uint2(bfbits(e0), bfbits(e1));
    }

    int rq0, rq1;
    {
        int ql = q0 + woff + gr;
        int i = ql / 24, j = ql - 24 * i;
        rq0 = reg1(sh * 24 + i) * 3 + reg1(sw * 24 + j);
        ql += 8; i = ql / 24; j = ql - 24 * i;
        rq1 = reg1(sh * 24 + i) * 3 + reg1(sw * 24 + j);
    }

    float O[8][4];
    #pragma unroll
    for (int nt = 0; nt < 8; ++nt)
        #pragma unroll
        for (int v = 0; v < 4; ++v) O[nt][v] = 0.0f;
    float l0s = 0.0f, l1s = 0.0f;

    const int kvsub = s << 4;      // kv half for S (16 rows)
    const int cbase = s << 6;      // channel half for PV
    const int barid = 1 + pair;

    for (int t = 0; t < NTILES; ++t) {
        const int kv0 = t * KVT;
        const int buf = t & 1;
        cp_wait_all();
        __syncthreads();   // tile t resident; all compute on buf^1 (t-1) done

        // ---- prefetch tile t+1 into buf^1 (overlaps with compute below) ----
        if (t + 1 < NTILES) {
            const int nb = buf ^ 1;
            const uint2* ksrc = g_Khl + wb64 + (size_t)(kv0 + KVT + kr) * 64;
            #pragma unroll
            for (int u = 0; u < 4; ++u) {
                int p  = kp + (u << 1);
                int pk = p ^ ((kr & 7) << 2);
                cp16(khl_b + (nb * 2048 + kr * 64 + pk) * 8, ksrc + p);
            }
            const float* vsrc = g_Vt + wb128 + (size_t)(kv0 + KVT + vr) * 128;
            #pragma unroll
            for (int u = 0; u < 4; ++u) {
                int c4 = vc + (u << 2);
                int cv = c4 ^ ((vr & 3) << 3);
                cp16(vs_b + (nb * 4096 + vr * 128 + cv) * 4, vsrc + c4);
            }
            cp_commit();
        }

        const uint2* KhlS = (const uint2*)(smem + KHL_W) + buf * 2048;
        const float* Vs   = smem + VS_W + buf * 4096;

        // ---- S = Q K^T (3xBF16) ----
        float S[2][4];
        #pragma unroll
        for (int nt = 0; nt < 2; ++nt)
            #pragma unroll
            for (int v = 0; v < 4; ++v) S[nt][v] = 0.0f;

        const int sA = gr << 2;
        #pragma unroll
        for (int st = 0; st < 8; ++st) {
            int pp  = (st << 3) + tig;
            int pA0 = pp ^ sA;
            int pA1 = (pp + 4) ^ sA;
            uint32_t ah0 = QhiS[(woff + gr) * 64 + pA0];
            uint32_t ah1 = QhiS[(woff + gr + 8) * 64 + pA0];
            uint32_t ah2 = QhiS[(woff + gr) * 64 + pA1];
            uint32_t ah3 = QhiS[(woff + gr + 8) * 64 + pA1];
            uint32_t al0 = QloS[(woff + gr) * 64 + pA0];
            uint32_t al1 = QloS[(woff + gr + 8) * 64 + pA0];
            uint32_t al2 = QloS[(woff + gr) * 64 + pA1];
            uint32_t al3 = QloS[(woff + gr + 8) * 64 + pA1];
            #pragma unroll
            for (int nt = 0; nt < 2; ++nt) {
                int kvr = kvsub + (nt << 3) + gr;       // (kvr&7)==gr
                uint2 b0 = KhlS[kvr * 64 + pA0];
                uint2 b1 = KhlS[kvr * 64 + pA1];
                mma16(S[nt], ah0, ah1, ah2, ah3, b0.x, b1.x);
                mma16(S[nt], ah0, ah1, ah2, ah3, b0.y, b1.y);
                mma16(S[nt], al0, al1, al2, al3, b0.x, b1.x);
            }
        }

        // ---- mask + exp (fixed-max) + stage P (tf32) + local l ----
        #pragma unroll
        for (int nt = 0; nt < 2; ++nt) {
            int kvb = kv0 + kvsub + (nt << 3) + (tig << 1);
            int rk0 = regK[kvb], rk1 = regK[kvb + 1];
            float p0 = __expf(rq0 != rk0 ? S[nt][0] - 100.0f : S[nt][0]);
            float p1 = __expf(rq0 != rk1 ? S[nt][1] - 100.0f : S[nt][1]);
            float p2 = __expf(rq1 != rk0 ? S[nt][2] - 100.0f : S[nt][2]);
            float p3 = __expf(rq1 != rk1 ? S[nt][3] - 100.0f : S[nt][3]);
            l0s += p0 + p1;
            l1s += p2 + p3;
            int c = kvsub + (nt << 3) + (tig << 1);
            uint32_t* pr0 = (uint32_t*)&Pb[(woff + gr) * P_PITCH + c];
            uint32_t* pr1 = (uint32_t*)&Pb[(woff + gr + 8) * P_PITCH + c];
            pr0[0] = f2tf(p0); pr0[1] = f2tf(p1);
            pr1[0] = f2tf(p2); pr1[1] = f2tf(p3);
        }
        // P handoff is pair-local: both warps of the pair wrote their kv
        // halves of rows woff..woff+15; both read the full 32 kv below.
        asm volatile("bar.sync %0, 64;" :: "r"(barid) : "memory");

        // ---- O += P @ V (tf32) on this warp's 64 channels ----
        const float* Pw = Pb + woff * P_PITCH;
        #pragma unroll
        for (int k8 = 0; k8 < KVT; k8 += 8) {
            uint32_t pa0 = __float_as_uint(Pw[gr * P_PITCH + k8 + tig]);
            uint32_t pa1 = __float_as_uint(Pw[(gr + 8) * P_PITCH + k8 + tig]);
            uint32_t pa2 = __float_as_uint(Pw[gr * P_PITCH + k8 + tig + 4]);
            uint32_t pa3 = __float_as_uint(Pw[(gr + 8) * P_PITCH + k8 + tig + 4]);
            int kvr = k8 + tig;
            int swv = (kvr & 3) << 3;
            #pragma unroll
            for (int nt = 0; nt < 8; ++nt) {
                int cv = (cbase + (nt << 3) + gr) ^ swv;
                uint32_t v0 = __float_as_uint(Vs[kvr * 128 + cv]);
                uint32_t v1 = __float_as_uint(Vs[(kvr + 4) * 128 + cv]);
                mma8(O[nt], pa0, pa1, pa2, pa3, v0, v1);
            }
        }
    }

    // ---- l reduction: quad shuffle, then cross-sub via smem ----
    l0s += __shfl_xor_sync(0xffffffffu, l0s, 1);
    l0s += __shfl_xor_sync(0xffffffffu, l0s, 2);
    l1s += __shfl_xor_sync(0xffffffffu, l1s, 1);
    l1s += __shfl_xor_sync(0xffffffffu, l1s, 2);
    __syncthreads();
    if (tig == 0) {
        SMB[(s << 6) + woff + gr]     = l0s;
        SMB[(s << 6) + woff + gr + 8] = l1s;
    }
    __syncthreads();
    float lt0 = SMB[woff + gr]     + SMB[64 + woff + gr];
    float lt1 = SMB[woff + gr + 8] + SMB[64 + woff + gr + 8];

    // ---- epilogue: normalize + scatter ----
    float inv0 = 1.0f / lt0, inv1 = 1.0f / lt1;
    int ql0 = q0 + woff + gr;
    int i0 = ql0 / 24, j0 = ql0 - 24 * i0;
    int gr0 = (sh * 24 + i0 + 12) % 96, gc0 = (sw * 24 + j0 + 12) % 96;
    int ql1 = ql0 + 8;
    int i1 = ql1 / 24, j1 = ql1 - 24 * i1;
    int gr1 = (sh * 24 + i1 + 12) % 96, gc1 = (sw * 24 + j1 + 12) % 96;
    float* d0 = outg + ((size_t)(b * 9216 + gr0 * 96 + gc0) << 7) + cbase;
    float* d1 = outg + ((size_t)(b * 9216 + gr1 * 96 + gc1) << 7) + cbase;
    #pragma unroll
    for (int nt = 0; nt < 8; ++nt) {
        int c = (nt << 3) + (tig << 1);
        *(float2*)(d0 + c) = make_float2(O[nt][0] * inv0, O[nt][1] * inv0);
        *(float2*)(d1 + c) = make_float2(O[nt][2] * inv1, O[nt][3] * inv1);
    }
}

extern "C" void kernel_launch(void* const* d_in, const int* in_sizes, int n_in,
                              void* d_out, int out_size)
{
    const float* q = (const float*)d_in[0];
    const float* k = (const float*)d_in[1];
    const float* v = (const float*)d_in[2];
    float* out = (float*)d_out;

    prep_kv<<<27648, 256>>>(k, v);

    cudaFuncSetAttribute(mv_attn_tc9,
                         cudaFuncAttributeMaxDynamicSharedMemorySize, SMEM_BYTES);
    dim3 grid(9, 128, 1);
    mv_attn_tc9<<<grid, NT, SMEM_BYTES>>>(q, out);
}

// round 12
// speedup vs baseline: 1.1584x; 1.0465x over previous
#include <cuda_runtime.h>
#include <cuda_fp16.h>
#include <cstdint>

// Shifted-window multi-view attention, v11 = v9 skeleton with fp16 QK split.
// B=8, M=3, H=W=96, C=128, NS=4 -> 128 windows, L=576, KV=1728.
//  prep_kv: gather K/V per window; K -> fp16 (hi,lo) interleaved uint2
//           (lo = fp16 residual); V -> tf32.
//  mv_attn_tc11: QK^T = 2-term fp16 m16n8k16: Qh*Kh + Qh*Kl, Q single-plane
//           fp16 in smem (dropped Ql*K term ~2.8e-4 abs in S — safe).
//           PV = tf32 m16n8k8. Fixed-max softmax (P=exp(S), scores O(5)),
//           l reduced once at end. KV tiles (KVT=32) double-buffered via
//           cp.async; 1 CTA sync + 1 pair-local named barrier per tile.
// CTA: 256 thr (8 warps), 64 q rows; warp pair owns 16 rows; sub s=warp&1:
// S on kv half (16 rows), PV on channel half (64).

#define NT 256
#define KVT 32
#define NTILES 54
#define NWIN 128
#define KVLEN 1728

__device__ uint2 g_Khl[(size_t)NWIN * KVLEN * 64];   // (hi,lo) fp16x2 per 2ch
__device__ float g_Vt [(size_t)NWIN * KVLEN * 128];  // tf32

// smem word offsets
#define QH_W    0          // u32 [64][64]           4096
#define KHL_W   4096       // uint2[2][32*64]        8192 words
#define VS_W    12288      // f32 [2][32][128]       8192
#define PB_W    20480      // f32 [64][36]           2304
#define SMB_W   22784      // f32 [2][64]            128
#define REGK_W  22912      // char[1728]             432 words
#define SMEM_BYTES (23344 * 4)   // 93376
#define P_PITCH 36

__device__ __forceinline__ uint32_t f2tf(float x) {
    uint32_t r; asm("cvt.rna.tf32.f32 %0, %1;" : "=r"(r) : "f"(x)); return r;
}
__device__ __forceinline__ uint32_t hbits(__half2 h) {
    return *reinterpret_cast<uint32_t*>(&h);
}
__device__ __forceinline__ void cp16(uint32_t dst, const void* src) {
    asm volatile("cp.async.cg.shared.global [%0], [%1], 16;" :: "r"(dst), "l"(src));
}
__device__ __forceinline__ void cp_commit() {
    asm volatile("cp.async.commit_group;" ::: "memory");
}
__device__ __forceinline__ void cp_wait_all() {
    asm volatile("cp.async.wait_group 0;" ::: "memory");
}
__device__ __forceinline__ void mma16h(float c[4],
    uint32_t a0, uint32_t a1, uint32_t a2, uint32_t a3, uint32_t b0, uint32_t b1) {
    asm volatile("mma.sync.aligned.m16n8k16.row.col.f32.f16.f16.f32 "
        "{%0,%1,%2,%3},{%4,%5,%6,%7},{%8,%9},{%0,%1,%2,%3};"
        : "+f"(c[0]), "+f"(c[1]), "+f"(c[2]), "+f"(c[3])
        : "r"(a0), "r"(a1), "r"(a2), "r"(a3), "r"(b0), "r"(b1));
}
__device__ __forceinline__ void mma8(float c[4],
    uint32_t a0, uint32_t a1, uint32_t a2, uint32_t a3, uint32_t b0, uint32_t b1) {
    asm volatile("mma.sync.aligned.m16n8k8.row.col.f32.tf32.tf32.f32 "
        "{%0,%1,%2,%3},{%4,%5,%6,%7},{%8,%9},{%0,%1,%2,%3};"
        : "+f"(c[0]), "+f"(c[1]), "+f"(c[2]), "+f"(c[3])
        : "r"(a0), "r"(a1), "r"(a2), "r"(a3), "r"(b0), "r"(b1));
}
__device__ __forceinline__ int reg1(int x) { return (x < 72) ? 0 : ((x < 84) ? 1 : 2); }

// ============ prep: gather + convert K/V ============
extern "C" __global__ void __launch_bounds__(256)
prep_kv(const float* __restrict__ kg, const float* __restrict__ vg)
{
    int g = blockIdx.x * 256 + threadIdx.x;     // 0 .. 128*1728*32-1
    int win = g / 55296;
    int rem = g - win * 55296;
    int kv  = rem >> 5;
    int c4  = (rem & 31) << 2;
    int b = win >> 4, sh = (win >> 2) & 3, sw = win & 3;
    int l = kv / 3, mm = kv - 3 * l;
    int i = l / 24, j = l - 24 * i;
    int grow = (sh * 24 + i + 12) % 96;
    int gcol = (sw * 24 + j + 12) % 96;
    size_t src = (((size_t)((b * 3 + mm) * 9216 + grow * 96 + gcol)) << 7) + c4;

    float4 kf = *(const float4*)(kg + src);
    __half2 h0 = __float22half2_rn(make_float2(kf.x, kf.y));
    __half2 h1 = __float22half2_rn(make_float2(kf.z, kf.w));
    float2 r0 = __half22float2(h0), r1 = __half22float2(h1);
    __half2 e0 = __float22half2_rn(make_float2(kf.x - r0.x, kf.y - r0.y));
    __half2 e1 = __float22half2_rn(make_float2(kf.z - r1.x, kf.w - r1.y));
    size_t dst = (size_t)win * (KVLEN * 64) + (size_t)kv * 64 + (c4 >> 1);
    *(uint4*)(g_Khl + dst) = make_uint4(hbits(h0), hbits(e0), hbits(h1), hbits(e1));

    float4 vf = *(const float4*)(vg + src);
    size_t dv = (size_t)win * (KVLEN * 128) + (size_t)kv * 128 + c4;
    *(uint4*)(g_Vt + dv) = make_uint4(f2tf(vf.x), f2tf(vf.y), f2tf(vf.z), f2tf(vf.w));
}

// ============ main attention kernel ============
extern "C" __global__ void __launch_bounds__(NT, 2)
mv_attn_tc11(const float* __restrict__ qg, float* __restrict__ outg)
{
    extern __shared__ float smem[];
    uint32_t* QhS = (uint32_t*)smem + QH_W;
    float*    Pb  = smem + PB_W;
    float*    SMB = smem + SMB_W;
    char*     regK = (char*)(smem + REGK_W);
    const uint32_t smem_u32 = (uint32_t)__cvta_generic_to_shared(smem);
    const uint32_t khl_b    = smem_u32 + KHL_W * 4;
    const uint32_t vs_b     = smem_u32 + VS_W * 4;

    const int tid  = threadIdx.x;
    const int warp = tid >> 5;
    const int lane = tid & 31;
    const int gr   = lane >> 2;
    const int tig  = lane & 3;
    const int pair = warp >> 1;
    const int s    = warp & 1;
    const int woff = pair << 4;

    const int win = blockIdx.y;
    const int b   = win >> 4;
    const int sh  = (win >> 2) & 3;
    const int sw  = win & 3;
    const int q0  = blockIdx.x << 6;

    const float scale = 0.08838834764831845f;   // 1/sqrt(128)
    const size_t wb64  = (size_t)win * (KVLEN * 64);
    const size_t wb128 = (size_t)win * (KVLEN * 128);

    // cp.async slot assignments (4 K + 4 V uint4 per thread per tile)
    const int kr = tid >> 3;
    const int kp = (tid & 7) << 3;
    const int vr = tid >> 3;
    const int vc = (tid & 7) << 4;

    // ---- region LUT (tile() quirk: mask column = kv % 576) ----
    for (int idx = tid; idx < KVLEN; idx += NT) {
        int kcol = idx % 576;
        int i = kcol / 24, j = kcol - 24 * i;
        regK[idx] = (char)(reg1(sh * 24 + i) * 3 + reg1(sw * 24 + j));
    }

    // ---- prefetch tile 0 into buffer 0 ----
    {
        const uint2* ksrc = g_Khl + wb64 + (size_t)kr * 64;
        #pragma unroll
        for (int u = 0; u < 4; ++u) {
            int p  = kp + (u << 1);
            int pk = p ^ ((kr & 7) << 2);
            cp16(khl_b + (kr * 64 + pk) * 8, ksrc + p);
        }
        const float* vsrc = g_Vt + wb128 + (size_t)vr * 128;
        #pragma unroll
        for (int u = 0; u < 4; ++u) {
            int c4 = vc + (u << 2);
            int cv = c4 ^ ((vr & 3) << 3);
            cp16(vs_b + (vr * 128 + cv) * 4, vsrc + c4);
        }
        cp_commit();
    }

    // ---- Q: gather + scale + single-plane fp16 into smem ----
    #pragma unroll
    for (int it = 0; it < 8; ++it) {
        int idx = tid + it * NT;
        int r   = idx >> 5;
        int c4  = (idx & 31) << 2;
        int ql  = q0 + r;
        int i = ql / 24, j = ql - 24 * i;
        int grow = (sh * 24 + i + 12) % 96;
        int gcol = (sw * 24 + j + 12) % 96;
        float4 f = *(const float4*)(qg + ((size_t)(b * 9216 + grow * 96 + gcol) << 7) + c4);
        __half2 h0 = __float22half2_rn(make_float2(f.x * scale, f.y * scale));
        __half2 h1 = __float22half2_rn(make_float2(f.z * scale, f.w * scale));
        int ps = (c4 >> 1) ^ ((r & 7) << 2);
        *(uint2*)&QhS[r * 64 + ps] = make_uint2(hbits(h0), hbits(h1));
    }

    int rq0, rq1;
    {
        int ql = q0 + woff + gr;
        int i = ql / 24, j = ql - 24 * i;
        rq0 = reg1(sh * 24 + i) * 3 + reg1(sw * 24 + j);
        ql += 8; i = ql / 24; j = ql - 24 * i;
        rq1 = reg1(sh * 24 + i) * 3 + reg1(sw * 24 + j);
    }

    float O[8][4];
    #pragma unroll
    for (int nt = 0; nt < 8; ++nt)
        #pragma unroll
        for (int v = 0; v < 4; ++v) O[nt][v] = 0.0f;
    float l0s = 0.0f, l1s = 0.0f;

    const int kvsub = s << 4;
    const int cbase = s << 6;
    const int barid = 1 + pair;

    for (int t = 0; t < NTILES; ++t) {
        const int kv0 = t * KVT;
        const int buf = t & 1;
        cp_wait_all();
        __syncthreads();   // tile t resident; compute on buf^1 (t-1) done

        if (t + 1 < NTILES) {   // prefetch tile t+1 into buf^1
            const int nb = buf ^ 1;
            const uint2* ksrc = g_Khl + wb64 + (size_t)(kv0 + KVT + kr) * 64;
            #pragma unroll
            for (int u = 0; u < 4; ++u) {
                int p  = kp + (u << 1);
                int pk = p ^ ((kr & 7) << 2);
                cp16(khl_b + (nb * 2048 + kr * 64 + pk) * 8, ksrc + p);
            }
            const float* vsrc = g_Vt + wb128 + (size_t)(kv0 + KVT + vr) * 128;
            #pragma unroll
            for (int u = 0; u < 4; ++u) {
                int c4 = vc + (u << 2);
                int cv = c4 ^ ((vr & 3) << 3);
                cp16(vs_b + (nb * 4096 + vr * 128 + cv) * 4, vsrc + c4);
            }
            cp_commit();
        }

        const uint2* KhlS = (const uint2*)(smem + KHL_W) + buf * 2048;
        const float* Vs   = smem + VS_W + buf * 4096;

        // ---- S = Qh·Kh + Qh·Kl (2-term fp16) ----
        float S[2][4];
        #pragma unroll
        for (int nt = 0; nt < 2; ++nt)
            #pragma unroll
            for (int v = 0; v < 4; ++v) S[nt][v] = 0.0f;

        const int sA = gr << 2;
        #pragma unroll
        for (int st = 0; st < 8; ++st) {
            int pp  = (st << 3) + tig;
            int pA0 = pp ^ sA;
            int pA1 = (pp + 4) ^ sA;
            uint32_t a0 = QhS[(woff + gr) * 64 + pA0];
            uint32_t a1 = QhS[(woff + gr + 8) * 64 + pA0];
            uint32_t a2 = QhS[(woff + gr) * 64 + pA1];
            uint32_t a3 = QhS[(woff + gr + 8) * 64 + pA1];
            #pragma unroll
            for (int nt = 0; nt < 2; ++nt) {
                int kvr = kvsub + (nt << 3) + gr;       // (kvr&7)==gr
                uint2 b0 = KhlS[kvr * 64 + pA0];
                uint2 b1 = KhlS[kvr * 64 + pA1];
                mma16h(S[nt], a0, a1, a2, a3, b0.x, b1.x);   // Qh*Kh
                mma16h(S[nt], a0, a1, a2, a3, b0.y, b1.y);   // Qh*Kl
            }
        }

        // ---- mask + exp (fixed-max) + stage P (tf32) + local l ----
        #pragma unroll
        for (int nt = 0; nt < 2; ++nt) {
            int kvb = kv0 + kvsub + (nt << 3) + (tig << 1);
            int rk0 = regK[kvb], rk1 = regK[kvb + 1];
            float p0 = __expf(rq0 != rk0 ? S[nt][0] - 100.0f : S[nt][0]);
            float p1 = __expf(rq0 != rk1 ? S[nt][1] - 100.0f : S[nt][1]);
            float p2 = __expf(rq1 != rk0 ? S[nt][2] - 100.0f : S[nt][2]);
            float p3 = __expf(rq1 != rk1 ? S[nt][3] - 100.0f : S[nt][3]);
            l0s += p0 + p1;
            l1s += p2 + p3;
            int c = kvsub + (nt << 3) + (tig << 1);
            uint32_t* pr0 = (uint32_t*)&Pb[(woff + gr) * P_PITCH + c];
            uint32_t* pr1 = (uint32_t*)&Pb[(woff + gr + 8) * P_PITCH + c];
            pr0[0] = f2tf(p0); pr0[1] = f2tf(p1);
            pr1[0] = f2tf(p2); pr1[1] = f2tf(p3);
        }
        asm volatile("bar.sync %0, 64;" :: "r"(barid) : "memory");   // pair-local

        // ---- O += P @ V (tf32) on this warp's 64 channels ----
        const float* Pw = Pb + woff * P_PITCH;
        #pragma unroll
        for (int k8 = 0; k8 < KVT; k8 += 8) {
            uint32_t pa0 = __float_as_uint(Pw[gr * P_PITCH + k8 + tig]);
            uint32_t pa1 = __float_as_uint(Pw[(gr + 8) * P_PITCH + k8 + tig]);
            uint32_t pa2 = __float_as_uint(Pw[gr * P_PITCH + k8 + tig + 4]);
            uint32_t pa3 = __float_as_uint(Pw[(gr + 8) * P_PITCH + k8 + tig + 4]);
            int kvr = k8 + tig;
            int swv = (kvr & 3) << 3;
            #pragma unroll
            for (int nt = 0; nt < 8; ++nt) {
                int cv = (cbase + (nt << 3) + gr) ^ swv;
                uint32_t v0 = __float_as_uint(Vs[kvr * 128 + cv]);
                uint32_t v1 = __float_as_uint(Vs[(kvr + 4) * 128 + cv]);
                mma8(O[nt], pa0, pa1, pa2, pa3, v0, v1);
            }
        }
    }

    // ---- l reduction: quad shuffle, then cross-sub via smem ----
    l0s += __shfl_xor_sync(0xffffffffu, l0s, 1);
    l0s += __shfl_xor_sync(0xffffffffu, l0s, 2);
    l1s += __shfl_xor_sync(0xffffffffu, l1s, 1);
    l1s += __shfl_xor_sync(0xffffffffu, l1s, 2);
    __syncthreads();
    if (tig == 0) {
        SMB[(s << 6) + woff + gr]     = l0s;
        SMB[(s << 6) + woff + gr + 8] = l1s;
    }
    __syncthreads();
    float lt0 = SMB[woff + gr]     + SMB[64 + woff + gr];
    float lt1 = SMB[woff + gr + 8] + SMB[64 + woff + gr + 8];

    // ---- epilogue: normalize + scatter ----
    float inv0 = 1.0f / lt0, inv1 = 1.0f / lt1;
    int ql0 = q0 + woff + gr;
    int i0 = ql0 / 24, j0 = ql0 - 24 * i0;
    int gr0 = (sh * 24 + i0 + 12) % 96, gc0 = (sw * 24 + j0 + 12) % 96;
    int ql1 = ql0 + 8;
    int i1 = ql1 / 24, j1 = ql1 - 24 * i1;
    int gr1 = (sh * 24 + i1 + 12) % 96, gc1 = (sw * 24 + j1 + 12) % 96;
    float* d0 = outg + ((size_t)(b * 9216 + gr0 * 96 + gc0) << 7) + cbase;
    float* d1 = outg + ((size_t)(b * 9216 + gr1 * 96 + gc1) << 7) + cbase;
    #pragma unroll
    for (int nt = 0; nt < 8; ++nt) {
        int c = (nt << 3) + (tig << 1);
        *(float2*)(d0 + c) = make_float2(O[nt][0] * inv0, O[nt][1] * inv0);
        *(float2*)(d1 + c) = make_float2(O[nt][2] * inv1, O[nt][3] * inv1);
    }
}

extern "C" void kernel_launch(void* const* d_in, const int* in_sizes, int n_in,
                              void* d_out, int out_size)
{
    const float* q = (const float*)d_in[0];
    const float* k = (const float*)d_in[1];
    const float* v = (const float*)d_in[2];
    float* out = (float*)d_out;

    prep_kv<<<27648, 256>>>(k, v);

    cudaFuncSetAttribute(mv_attn_tc11,
                         cudaFuncAttributeMaxDynamicSharedMemorySize, SMEM_BYTES);
    dim3 grid(9, 128, 1);
    mv_attn_tc11<<<grid, NT, SMEM_BYTES>>>(q, out);
}

// round 13
// speedup vs baseline: 1.5914x; 1.3739x over previous
#include <cuda_runtime.h>
#include <cuda_fp16.h>
#include <cstdint>

// v12 = v11 (2-term fp16 QK) + fp16 PV with transposed V.
// B=8, M=3, H=W=96, C=128, NS=4 -> 128 windows, L=576, KV=1728.
//  prep_kv2: gather per window; K -> fp16 (hi,lo) interleaved uint2;
//            V -> fp16 TRANSPOSED [win][tile][ch][kvpair] fp16x2.
//  mv_attn_tc12: QK^T = Qh*Kh + Qh*Kl (fp16 m16n8k16, Q single-plane).
//            PV = fp16 m16n8k16 (P,V fp16; R7-calibrated error ~2.9e-4).
//            Fixed-max softmax; l reduced once at end; cp.async
//            double-buffered KV; 1 CTA sync + 1 pair-local bar per tile.
// CTA: 256 thr (8 warps), 64 q rows; warp pair owns 16 rows; sub s=warp&1:
// S on kv half (16 rows), PV on channel half (64). KVT=32.

#define NT 256
#define KVT 32
#define NTILES 54
#define NWIN 128
#define KVLEN 1728

__device__ uint2    g_Khl [(size_t)NWIN * KVLEN * 64];     // (hi,lo) fp16x2 / 2ch
__device__ uint32_t g_Vt16[(size_t)NWIN * NTILES * 2048];  // [win][tile][ch 128][pair 16]

// smem word offsets
#define QH_W    0          // u32 [64][64]             4096
#define KHL_W   4096       // uint2[2][32*64]          8192 words
#define VT_W    12288      // u32 [2][128][20]         5120
#define PB_W    17408      // u32 [64][20]             1280
#define SMB_W   18688      // f32 [2][64]              128
#define REGK_W  18816      // char[1728]               432 words
#define SMEM_BYTES (19248 * 4)   // 76992

__device__ __forceinline__ uint32_t hbits(__half2 h) {
    return *reinterpret_cast<uint32_t*>(&h);
}
__device__ __forceinline__ void cp16(uint32_t dst, const void* src) {
    asm volatile("cp.async.cg.shared.global [%0], [%1], 16;" :: "r"(dst), "l"(src));
}
__device__ __forceinline__ void cp_commit() {
    asm volatile("cp.async.commit_group;" ::: "memory");
}
__device__ __forceinline__ void cp_wait_all() {
    asm volatile("cp.async.wait_group 0;" ::: "memory");
}
__device__ __forceinline__ void mma16h(float c[4],
    uint32_t a0, uint32_t a1, uint32_t a2, uint32_t a3, uint32_t b0, uint32_t b1) {
    asm volatile("mma.sync.aligned.m16n8k16.row.col.f32.f16.f16.f32 "
        "{%0,%1,%2,%3},{%4,%5,%6,%7},{%8,%9},{%0,%1,%2,%3};"
        : "+f"(c[0]), "+f"(c[1]), "+f"(c[2]), "+f"(c[3])
        : "r"(a0), "r"(a1), "r"(a2), "r"(a3), "r"(b0), "r"(b1));
}
__device__ __forceinline__ int reg1(int x) { return (x < 72) ? 0 : ((x < 84) ? 1 : 2); }

// ============ prep: gather+convert K, gather+transpose V ============
// block = (win, 64-kv chunk) -> covers 2 KV tiles. 128*27 blocks.
extern "C" __global__ void __launch_bounds__(256)
prep_kv2(const float* __restrict__ kg, const float* __restrict__ vg)
{
    __shared__ uint16_t sv[128 * 64];   // [ch][kv] fp16, swizzled
    const int tid = threadIdx.x, blk = blockIdx.x;
    const int win = blk / 27, kb = blk - win * 27;
    const int kvbase = kb * 64;
    const int b = win >> 4, sh = (win >> 2) & 3, sw = win & 3;

    #pragma unroll
    for (int e = 0; e < 8; ++e) {
        int idx = tid + e * 256;
        int kvl = idx >> 5, c4 = (idx & 31) << 2;
        int kv = kvbase + kvl;
        int l = kv / 3, mm = kv - 3 * l;
        int i = l / 24, j = l - 24 * i;
        int grow = (sh * 24 + i + 12) % 96;
        int gcol = (sw * 24 + j + 12) % 96;
        size_t src = (((size_t)((b * 3 + mm) * 9216 + grow * 96 + gcol)) << 7) + c4;

        float4 kf = *(const float4*)(kg + src);
        __half2 h0 = __floats2half2_rn(kf.x, kf.y);
        __half2 h1 = __floats2half2_rn(kf.z, kf.w);
        float2 r0 = __half22float2(h0), r1 = __half22float2(h1);
        __half2 e0 = __floats2half2_rn(kf.x - r0.x, kf.y - r0.y);
        __half2 e1 = __floats2half2_rn(kf.z - r1.x, kf.w - r1.y);
        size_t dst = (size_t)win * (KVLEN * 64) + (size_t)kv * 64 + (c4 >> 1);
        *(uint4*)(g_Khl + dst) = make_uint4(hbits(h0), hbits(e0), hbits(h1), hbits(e1));

        float4 vf = *(const float4*)(vg + src);
        float vv[4] = {vf.x, vf.y, vf.z, vf.w};
        #pragma unroll
        for (int k2 = 0; k2 < 4; ++k2) {
            int ch = c4 + k2;
            __half vh = __float2half_rn(vv[k2]);
            sv[ch * 64 + (kvl ^ ((ch & 31) << 1))] = *reinterpret_cast<uint16_t*>(&vh);
        }
    }
    __syncthreads();

    const uint32_t* svw = (const uint32_t*)sv;   // [ch][32 pairs] swizzled
    #pragma unroll
    for (int it = 0; it < 16; ++it) {
        int idx = tid + it * 256;          // 4096 = 128 ch x 32 pairs
        int ch = idx >> 5, kp = idx & 31;
        uint32_t w = svw[ch * 32 + (kp ^ (ch & 31))];
        int tile = kb * 2 + (kp >> 4);
        int pr   = kp & 15;
        g_Vt16[(size_t)(win * NTILES + tile) * 2048 + ch * 16 + pr] = w;
    }
}

// ============ main attention kernel ============
extern "C" __global__ void __launch_bounds__(NT, 2)
mv_attn_tc12(const float* __restrict__ qg, float* __restrict__ outg)
{
    extern __shared__ float smem[];
    uint32_t* QhS = (uint32_t*)smem + QH_W;
    uint32_t* PbU = (uint32_t*)smem + PB_W;
    float*    SMB = smem + SMB_W;
    char*     regK = (char*)(smem + REGK_W);
    const uint32_t smem_u32 = (uint32_t)__cvta_generic_to_shared(smem);
    const uint32_t khl_b = smem_u32 + KHL_W * 4;
    const uint32_t vt_b  = smem_u32 + VT_W * 4;

    const int tid  = threadIdx.x;
    const int warp = tid >> 5;
    const int lane = tid & 31;
    const int gr   = lane >> 2;
    const int tig  = lane & 3;
    const int pair = warp >> 1;
    const int s    = warp & 1;
    const int woff = pair << 4;

    const int win = blockIdx.y;
    const int b   = win >> 4;
    const int sh  = (win >> 2) & 3;
    const int sw  = win & 3;
    const int q0  = blockIdx.x << 6;

    const float scale = 0.08838834764831845f;   // 1/sqrt(128)
    const size_t wb64 = (size_t)win * (KVLEN * 64);

    // cp.async slots: K 4 chunks/thread, V 2 chunks/thread
    const int kr = tid >> 3;
    const int kp = (tid & 7) << 3;

    // ---- region LUT (tile() quirk: mask column = kv % 576) ----
    for (int idx = tid; idx < KVLEN; idx += NT) {
        int kcol = idx % 576;
        int i = kcol / 24, j = kcol - 24 * i;
        regK[idx] = (char)(reg1(sh * 24 + i) * 3 + reg1(sw * 24 + j));
    }

    // ---- prefetch tile 0 into buffer 0 ----
    {
        const uint2* ksrc = g_Khl + wb64 + (size_t)kr * 64;
        #pragma unroll
        for (int u = 0; u < 4; ++u) {
            int p  = kp + (u << 1);
            int pk = p ^ ((kr & 7) << 2);
            cp16(khl_b + (kr * 64 + pk) * 8, ksrc + p);
        }
        const uint32_t* vsrc = g_Vt16 + (size_t)(win * NTILES) * 2048;
        #pragma unroll
        for (int u = 0; u < 2; ++u) {
            int c = tid + u * 256;
            int ch = c >> 2, grp = c & 3;
            cp16(vt_b + (ch * 20 + grp * 4) * 4, vsrc + ch * 16 + grp * 4);
        }
        cp_commit();
    }

    // ---- Q: gather + scale + single-plane fp16 into smem ----
    #pragma unroll
    for (int it = 0; it < 8; ++it) {
        int idx = tid + it * NT;
        int r   = idx >> 5;
        int c4  = (idx & 31) << 2;
        int ql  = q0 + r;
        int i = ql / 24, j = ql - 24 * i;
        int grow = (sh * 24 + i + 12) % 96;
        int gcol = (sw * 24 + j + 12) % 96;
        float4 f = *(const float4*)(qg + ((size_t)(b * 9216 + grow * 96 + gcol) << 7) + c4);
        __half2 h0 = __floats2half2_rn(f.x * scale, f.y * scale);
        __half2 h1 = __floats2half2_rn(f.z * scale, f.w * scale);
        int ps = (c4 >> 1) ^ ((r & 7) << 2);
        *(uint2*)&QhS[r * 64 + ps] = make_uint2(hbits(h0), hbits(h1));
    }

    int rq0, rq1;
    {
        int ql = q0 + woff + gr;
        int i = ql / 24, j = ql - 24 * i;
        rq0 = reg1(sh * 24 + i) * 3 + reg1(sw * 24 + j);
        ql += 8; i = ql / 24; j = ql - 24 * i;
        rq1 = reg1(sh * 24 + i) * 3 + reg1(sw * 24 + j);
    }

    float O[8][4];
    #pragma unroll
    for (int nt = 0; nt < 8; ++nt)
        #pragma unroll
        for (int v = 0; v < 4; ++v) O[nt][v] = 0.0f;
    float l0s = 0.0f, l1s = 0.0f;

    const int kvsub = s << 4;      // kv half for S (16 rows)
    const int pbase = s << 3;      // pair base for P staging
    const int cbase = s << 6;      // channel half for PV
    const int barid = 1 + pair;

    for (int t = 0; t < NTILES; ++t) {
        const int kv0 = t * KVT;
        const int buf = t & 1;
        cp_wait_all();
        __syncthreads();   // tile t resident; compute on buf^1 (t-1) done

        if (t + 1 < NTILES) {   // prefetch tile t+1 into buf^1
            const int nb = buf ^ 1;
            const uint2* ksrc = g_Khl + wb64 + (size_t)(kv0 + KVT + kr) * 64;
            #pragma unroll
            for (int u = 0; u < 4; ++u) {
                int p  = kp + (u << 1);
                int pk = p ^ ((kr & 7) << 2);
                cp16(khl_b + (nb * 2048 + kr * 64 + pk) * 8, ksrc + p);
            }
            const uint32_t* vsrc = g_Vt16 + (size_t)(win * NTILES + t + 1) * 2048;
            #pragma unroll
            for (int u = 0; u < 2; ++u) {
                int c = tid + u * 256;
                int ch = c >> 2, grp = c & 3;
                cp16(vt_b + (nb * 2560 + ch * 20 + grp * 4) * 4, vsrc + ch * 16 + grp * 4);
            }
            cp_commit();
        }

        const uint2*    KhlS = (const uint2*)(smem + KHL_W) + buf * 2048;
        const uint32_t* Vt   = (const uint32_t*)smem + VT_W + buf * 2560;

        // ---- S = Qh·Kh + Qh·Kl (2-term fp16) ----
        float S[2][4];
        #pragma unroll
        for (int nt = 0; nt < 2; ++nt)
            #pragma unroll
            for (int v = 0; v < 4; ++v) S[nt][v] = 0.0f;

        const int sA = gr << 2;
        #pragma unroll
        for (int st = 0; st < 8; ++st) {
            int pp  = (st << 3) + tig;
            int pA0 = pp ^ sA;
            int pA1 = (pp + 4) ^ sA;
            uint32_t a0 = QhS[(woff + gr) * 64 + pA0];
            uint32_t a1 = QhS[(woff + gr + 8) * 64 + pA0];
            uint32_t a2 = QhS[(woff + gr) * 64 + pA1];
            uint32_t a3 = QhS[(woff + gr + 8) * 64 + pA1];
            #pragma unroll
            for (int nt = 0; nt < 2; ++nt) {
                int kvr = kvsub + (nt << 3) + gr;       // (kvr&7)==gr
                uint2 b0 = KhlS[kvr * 64 + pA0];
                uint2 b1 = KhlS[kvr * 64 + pA1];
                mma16h(S[nt], a0, a1, a2, a3, b0.x, b1.x);   // Qh*Kh
                mma16h(S[nt], a0, a1, a2, a3, b0.y, b1.y);   // Qh*Kl
            }
        }

        // ---- mask + exp (fixed-max) + stage P (fp16x2, pitch 20) + local l ----
        #pragma unroll
        for (int nt = 0; nt < 2; ++nt) {
            int kvb = kv0 + kvsub + (nt << 3) + (tig << 1);
            int rk0 = regK[kvb], rk1 = regK[kvb + 1];
            float p0 = __expf(rq0 != rk0 ? S[nt][0] - 100.0f : S[nt][0]);
            float p1 = __expf(rq0 != rk1 ? S[nt][1] - 100.0f : S[nt][1]);
            float p2 = __expf(rq1 != rk0 ? S[nt][2] - 100.0f : S[nt][2]);
            float p3 = __expf(rq1 != rk1 ? S[nt][3] - 100.0f : S[nt][3]);
            l0s += p0 + p1;
            l1s += p2 + p3;
            int pc = pbase + (nt << 2) + tig;   // pair column
            PbU[(woff + gr) * 20 + pc]     = hbits(__floats2half2_rn(p0, p1));
            PbU[(woff + gr + 8) * 20 + pc] = hbits(__floats2half2_rn(p2, p3));
        }
        asm volatile("bar.sync %0, 64;" :: "r"(barid) : "memory");   // pair-local

        // ---- O += P @ V (fp16 m16n8k16) on this warp's 64 channels ----
        const uint32_t* Pw = PbU + woff * 20;
        #pragma unroll
        for (int st = 0; st < 2; ++st) {
            int pb = (st << 3) + tig;
            uint32_t a0 = Pw[gr * 20 + pb];
            uint32_t a1 = Pw[(gr + 8) * 20 + pb];
            uint32_t a2 = Pw[gr * 20 + pb + 4];
            uint32_t a3 = Pw[(gr + 8) * 20 + pb + 4];
            #pragma unroll
            for (int nt = 0; nt < 8; ++nt) {
                int ch = cbase + (nt << 3) + gr;
                uint32_t v0 = Vt[ch * 20 + pb];
                uint32_t v1 = Vt[ch * 20 + pb + 4];
                mma16h(O[nt], a0, a1, a2, a3, v0, v1);
            }
        }
    }

    // ---- l reduction: quad shuffle, then cross-sub via smem ----
    l0s += __shfl_xor_sync(0xffffffffu, l0s, 1);
    l0s += __shfl_xor_sync(0xffffffffu, l0s, 2);
    l1s += __shfl_xor_sync(0xffffffffu, l1s, 1);
    l1s += __shfl_xor_sync(0xffffffffu, l1s, 2);
    __syncthreads();
    if (tig == 0) {
        SMB[(s << 6) + woff + gr]     = l0s;
        SMB[(s << 6) + woff + gr + 8] = l1s;
    }
    __syncthreads();
    float lt0 = SMB[woff + gr]     + SMB[64 + woff + gr];
    float lt1 = SMB[woff + gr + 8] + SMB[64 + woff + gr + 8];

    // ---- epilogue: normalize + scatter ----
    float inv0 = 1.0f / lt0, inv1 = 1.0f / lt1;
    int ql0 = q0 + woff + gr;
    int i0 = ql0 / 24, j0 = ql0 - 24 * i0;
    int gr0 = (sh * 24 + i0 + 12) % 96, gc0 = (sw * 24 + j0 + 12) % 96;
    int ql1 = ql0 + 8;
    int i1 = ql1 / 24, j1 = ql1 - 24 * i1;
    int gr1 = (sh * 24 + i1 + 12) % 96, gc1 = (sw * 24 + j1 + 12) % 96;
    float* d0 = outg + ((size_t)(b * 9216 + gr0 * 96 + gc0) << 7) + cbase;
    float* d1 = outg + ((size_t)(b * 9216 + gr1 * 96 + gc1) << 7) + cbase;
    #pragma unroll
    for (int nt = 0; nt < 8; ++nt) {
        int c = (nt << 3) + (tig << 1);
        *(float2*)(d0 + c) = make_float2(O[nt][0] * inv0, O[nt][1] * inv0);
        *(float2*)(d1 + c) = make_float2(O[nt][2] * inv1, O[nt][3] * inv1);
    }
}

extern "C" void kernel_launch(void* const* d_in, const int* in_sizes, int n_in,
                              void* d_out, int out_size)
{
    const float* q = (const float*)d_in[0];
    const float* k = (const float*)d_in[1];
    const float* v = (const float*)d_in[2];
    float* out = (float*)d_out;

    prep_kv2<<<NWIN * 27, 256>>>(k, v);

    cudaFuncSetAttribute(mv_attn_tc12,
                         cudaFuncAttributeMaxDynamicSharedMemorySize, SMEM_BYTES);
    dim3 grid(9, 128, 1);
    mv_attn_tc12<<<grid, NT, SMEM_BYTES>>>(q, out);
}